// round 1
// baseline (speedup 1.0000x reference)
#include <cuda_runtime.h>
#include <math.h>
#include <stdint.h>

#define N_NODES   16384
#define N_GRAPHS  64
#define NPG       256
#define F_IN      128
#define E_DIM     256
#define N_HEADS   8
#define DH        32
#define MLP_DIM   1024
#define N_LAYERS  4
#define N_CLASSES 10
#define N_EDGES   262144
#define SEQ       257                 // NODES_PER_GRAPH + 1 (cls)
#define TOK       (N_GRAPHS * SEQ)    // 16448
#define LN_EPS    1e-5f

// ---------------- scratch (static device allocations, allowed) -------------
__device__ float g_xw [N_NODES * F_IN];       // x @ gcn_w^T
__device__ float g_gcn[N_NODES * F_IN];       // gcn aggregate / relu'd
__device__ float g_deg [N_NODES];
__device__ float g_dinv[N_NODES];
__device__ float g_emb[N_NODES * E_DIM];      // embedded nodes
__device__ float g_h  [TOK * E_DIM];          // running hidden state H
__device__ float g_qkv[TOK * 3 * E_DIM];
__device__ float g_att[TOK * E_DIM];          // attention output (pre-proj)
__device__ float g_tmp[TOK * E_DIM];          // residual-added pre-LN
__device__ float g_mlp[TOK * MLP_DIM];

// ---------------- generic tiled GEMM: C = A[M,K] * B[N,K]^T (+bias)(+add)(relu)
// Requires M%64==0, N%64==0, K%16==0 (all call sites satisfy this).
template <int RELU>
__global__ __launch_bounds__(256)
void gemm64(const float* __restrict__ A, const float* __restrict__ B,
            const float* __restrict__ bias, const float* __restrict__ add,
            float* __restrict__ C, int M, int N, int K)
{
    __shared__ float As[16][64];
    __shared__ float Bs[16][64];

    const int m0 = blockIdx.y * 64;
    const int n0 = blockIdx.x * 64;
    const int t  = threadIdx.x;          // 0..255
    const int lr = t >> 2;               // load row 0..63
    const int lc = t & 3;                // float4 index 0..3
    const int tx = t & 15;               // col group
    const int ty = t >> 4;               // row group

    float acc[4][4];
#pragma unroll
    for (int i = 0; i < 4; i++)
#pragma unroll
        for (int j = 0; j < 4; j++) acc[i][j] = 0.f;

    for (int k0 = 0; k0 < K; k0 += 16) {
        float4 av = *(const float4*)&A[(size_t)(m0 + lr) * K + k0 + lc * 4];
        float4 bv = *(const float4*)&B[(size_t)(n0 + lr) * K + k0 + lc * 4];
        As[lc * 4 + 0][lr] = av.x; As[lc * 4 + 1][lr] = av.y;
        As[lc * 4 + 2][lr] = av.z; As[lc * 4 + 3][lr] = av.w;
        Bs[lc * 4 + 0][lr] = bv.x; Bs[lc * 4 + 1][lr] = bv.y;
        Bs[lc * 4 + 2][lr] = bv.z; Bs[lc * 4 + 3][lr] = bv.w;
        __syncthreads();
#pragma unroll
        for (int kk = 0; kk < 16; kk++) {
            float4 a = *(const float4*)&As[kk][ty * 4];
            float4 b = *(const float4*)&Bs[kk][tx * 4];
            float ar[4] = {a.x, a.y, a.z, a.w};
            float br[4] = {b.x, b.y, b.z, b.w};
#pragma unroll
            for (int i = 0; i < 4; i++)
#pragma unroll
                for (int j = 0; j < 4; j++) acc[i][j] += ar[i] * br[j];
        }
        __syncthreads();
    }

#pragma unroll
    for (int i = 0; i < 4; i++) {
        int m = m0 + ty * 4 + i;
#pragma unroll
        for (int j = 0; j < 4; j++) {
            int n = n0 + tx * 4 + j;
            float v = acc[i][j];
            if (bias) v += bias[n];
            size_t idx = (size_t)m * N + n;
            if (add) v += add[idx];
            if (RELU) v = v > 0.f ? v : 0.f;
            C[idx] = v;
        }
    }
}

// ---------------- GCN pieces ----------------------------------------------
__global__ void deg_init_k() {
    int i = blockIdx.x * blockDim.x + threadIdx.x;
    if (i < N_NODES) g_deg[i] = 1.0f;          // self-loop
}
__global__ void deg_count_k(const int* __restrict__ ei) {
    int i = blockIdx.x * blockDim.x + threadIdx.x;
    for (; i < N_EDGES; i += gridDim.x * blockDim.x)
        atomicAdd(&g_deg[ei[N_EDGES + i]], 1.0f);
}
__global__ void dinv_k() {
    int i = blockIdx.x * blockDim.x + threadIdx.x;
    if (i < N_NODES) g_dinv[i] = rsqrtf(g_deg[i]);
}
__global__ void gcn_self_k() {
    int i = blockIdx.x * blockDim.x + threadIdx.x;
    if (i < N_NODES * F_IN) {
        int n = i >> 7;
        float d = g_dinv[n];
        g_gcn[i] = d * d * g_xw[i];
    }
}
__global__ void gcn_scatter_k(const int* __restrict__ ei) {
    int warp = (blockIdx.x * blockDim.x + threadIdx.x) >> 5;
    int lane = threadIdx.x & 31;
    int nwarp = (gridDim.x * blockDim.x) >> 5;
    for (int e = warp; e < N_EDGES; e += nwarp) {
        int row = ei[e];
        int col = ei[N_EDGES + e];
        float nm = g_dinv[row] * g_dinv[col];
        const float* src = g_xw + (size_t)row * F_IN;
        float* dst = g_gcn + (size_t)col * F_IN;
#pragma unroll
        for (int j = 0; j < 4; j++)
            atomicAdd(&dst[lane + 32 * j], nm * src[lane + 32 * j]);
    }
}
__global__ void gcn_bias_relu_k(const float* __restrict__ b) {
    int i = blockIdx.x * blockDim.x + threadIdx.x;
    if (i < N_NODES * F_IN) {
        float v = g_gcn[i] + b[i & 127];
        g_gcn[i] = v > 0.f ? v : 0.f;
    }
}

// ---------------- assemble H (cls token + embedded nodes) ------------------
__global__ void assemble_k(const float* __restrict__ cls) {
    int idx = blockIdx.x * blockDim.x + threadIdx.x;   // TOK*E_DIM exact
    int row = idx >> 8, col = idx & 255;
    int g = row / SEQ, s = row - g * SEQ;
    g_h[idx] = (s == 0) ? cls[col]
                        : g_emb[((size_t)(g * NPG + s - 1)) * E_DIM + col];
}

// ---------------- attention: one block per (graph, head) -------------------
__global__ __launch_bounds__(288)
void attn_k(const float* __restrict__ qkv, float* __restrict__ O)
{
    const int g  = blockIdx.x >> 3;
    const int hd = blockIdx.x & 7;
    __shared__ float Ks[128][DH];
    __shared__ float Vs[128][DH];

    const int tid = threadIdx.x;          // 288
    const int r = tid;
    const bool act = r < SEQ;
    const float scale = 0.17677669529663687f;   // 1/sqrt(32)

    float q[DH], acc[DH];
    float m = -1e30f, l = 0.f;
    if (act) {
        const float* qp = qkv + ((size_t)(g * SEQ + r)) * 768 + hd * DH;
#pragma unroll
        for (int d = 0; d < DH; d++) { q[d] = qp[d] * scale; acc[d] = 0.f; }
    }

    for (int c0 = 0; c0 < SEQ; c0 += 128) {
        int nk = SEQ - c0; if (nk > 128) nk = 128;
        __syncthreads();
        for (int i = tid; i < nk * DH; i += blockDim.x) {
            int kk = i >> 5, d = i & 31;
            const float* base = qkv + ((size_t)(g * SEQ + c0 + kk)) * 768
                              + E_DIM + hd * DH + d;
            Ks[kk][d] = base[0];
            Vs[kk][d] = base[E_DIM];
        }
        __syncthreads();
        if (act) {
            for (int kk = 0; kk < nk; kk++) {
                float s = 0.f;
#pragma unroll
                for (int d = 0; d < DH; d++) s += q[d] * Ks[kk][d];
                if (s <= m) {
                    float p = __expf(s - m);
                    l += p;
#pragma unroll
                    for (int d = 0; d < DH; d++) acc[d] += p * Vs[kk][d];
                } else {
                    float corr = __expf(m - s);
                    m = s;
                    l = l * corr + 1.f;
#pragma unroll
                    for (int d = 0; d < DH; d++) acc[d] = acc[d] * corr + Vs[kk][d];
                }
            }
        }
    }
    if (act) {
        float inv = 1.f / l;
        float* op = O + ((size_t)(g * SEQ + r)) * E_DIM + hd * DH;
#pragma unroll
        for (int d = 0; d < DH; d++) op[d] = acc[d] * inv;
    }
}

// ---------------- layernorm: one block (256 threads) per row ---------------
__global__ __launch_bounds__(256)
void ln_k(const float* __restrict__ in, const float* __restrict__ gam,
          const float* __restrict__ bet, float* __restrict__ out)
{
    const int row = blockIdx.x, t = threadIdx.x;
    const size_t base = (size_t)row * E_DIM;
    float v = in[base + t];

    __shared__ float red[8];
    __shared__ float bc;
    float s = v;
#pragma unroll
    for (int o = 16; o; o >>= 1) s += __shfl_xor_sync(0xffffffffu, s, o);
    if ((t & 31) == 0) red[t >> 5] = s;
    __syncthreads();
    if (t == 0) {
        float tt = 0.f;
#pragma unroll
        for (int i = 0; i < 8; i++) tt += red[i];
        bc = tt * (1.f / E_DIM);
    }
    __syncthreads();
    float mu = bc;
    float d = v - mu;
    __syncthreads();
    s = d * d;
#pragma unroll
    for (int o = 16; o; o >>= 1) s += __shfl_xor_sync(0xffffffffu, s, o);
    if ((t & 31) == 0) red[t >> 5] = s;
    __syncthreads();
    if (t == 0) {
        float tt = 0.f;
#pragma unroll
        for (int i = 0; i < 8; i++) tt += red[i];
        bc = rsqrtf(tt * (1.f / E_DIM) + LN_EPS);
    }
    __syncthreads();
    out[base + t] = d * bc * gam[t] + bet[t];
}

// ---------------- final classifier -----------------------------------------
__global__ __launch_bounds__(256)
void fc_k(const float* __restrict__ w, const float* __restrict__ b,
          float* __restrict__ out)
{
    const int g = blockIdx.x, t = threadIdx.x;
    __shared__ float hrow[E_DIM];
    hrow[t] = g_h[(size_t)g * SEQ * E_DIM + t];
    __syncthreads();
    if (t < N_CLASSES) {
        float s = b[t];
        for (int e = 0; e < E_DIM; e++) s += hrow[e] * w[t * E_DIM + e];
        out[g * N_CLASSES + t] = s;
    }
}

// ---------------------------------------------------------------------------
extern "C" void kernel_launch(void* const* d_in, const int* in_sizes, int n_in,
                              void* d_out, int out_size)
{
    const float* x        = (const float*)d_in[0];
    const int*   edge_idx = (const int*)  d_in[1];
    // d_in[2] = batch (unused: layout is arange // NPG by construction)
    const float* pos_enc  = (const float*)d_in[3];
    const float* gcn_w    = (const float*)d_in[4];
    const float* gcn_b    = (const float*)d_in[5];
    const float* cls      = (const float*)d_in[6];
    const float* emb_w    = (const float*)d_in[7];
    const float* emb_b    = (const float*)d_in[8];
    const float* in_w     = (const float*)d_in[9];
    const float* in_b     = (const float*)d_in[10];
    const float* out_w    = (const float*)d_in[11];
    const float* out_b    = (const float*)d_in[12];
    const float* lin1_w   = (const float*)d_in[13];
    const float* lin1_b   = (const float*)d_in[14];
    const float* lin2_w   = (const float*)d_in[15];
    const float* lin2_b   = (const float*)d_in[16];
    const float* ln1_g    = (const float*)d_in[17];
    const float* ln1_beta = (const float*)d_in[18];
    const float* ln2_g    = (const float*)d_in[19];
    const float* ln2_beta = (const float*)d_in[20];
    const float* fc_w     = (const float*)d_in[21];
    const float* fc_b     = (const float*)d_in[22];
    float* out = (float*)d_out;

    void *p;
    float *xw, *gcn, *emb, *h, *qkv, *att, *tmp, *mlp;
    cudaGetSymbolAddress(&p, g_xw);  xw  = (float*)p;
    cudaGetSymbolAddress(&p, g_gcn); gcn = (float*)p;
    cudaGetSymbolAddress(&p, g_emb); emb = (float*)p;
    cudaGetSymbolAddress(&p, g_h);   h   = (float*)p;
    cudaGetSymbolAddress(&p, g_qkv); qkv = (float*)p;
    cudaGetSymbolAddress(&p, g_att); att = (float*)p;
    cudaGetSymbolAddress(&p, g_tmp); tmp = (float*)p;
    cudaGetSymbolAddress(&p, g_mlp); mlp = (float*)p;

    // ---- GCN front-end ----
    gemm64<0><<<dim3(F_IN / 64, N_NODES / 64), 256>>>(
        x, gcn_w, nullptr, nullptr, xw, N_NODES, F_IN, F_IN);
    deg_init_k<<<N_NODES / 256, 256>>>();
    deg_count_k<<<512, 256>>>(edge_idx);
    dinv_k<<<N_NODES / 256, 256>>>();
    gcn_self_k<<<(N_NODES * F_IN) / 256, 256>>>();
    gcn_scatter_k<<<2048, 256>>>(edge_idx);
    gcn_bias_relu_k<<<(N_NODES * F_IN) / 256, 256>>>(gcn_b);

    // ---- embedding + pos_enc, assemble tokens ----
    gemm64<0><<<dim3(E_DIM / 64, N_NODES / 64), 256>>>(
        gcn, emb_w, emb_b, pos_enc, emb, N_NODES, E_DIM, F_IN);
    assemble_k<<<(TOK * E_DIM) / 256, 256>>>(cls);

    // ---- transformer layers ----
    for (int l = 0; l < N_LAYERS; l++) {
        gemm64<0><<<dim3(768 / 64, TOK / 64), 256>>>(
            h, in_w + (size_t)l * 768 * E_DIM, in_b + l * 768,
            nullptr, qkv, TOK, 768, E_DIM);
        attn_k<<<N_GRAPHS * N_HEADS, 288>>>(qkv, att);
        gemm64<0><<<dim3(E_DIM / 64, TOK / 64), 256>>>(
            att, out_w + (size_t)l * E_DIM * E_DIM, out_b + l * E_DIM,
            h, tmp, TOK, E_DIM, E_DIM);
        ln_k<<<TOK, 256>>>(tmp, ln1_g + l * E_DIM, ln1_beta + l * E_DIM, h);
        gemm64<1><<<dim3(MLP_DIM / 64, TOK / 64), 256>>>(
            h, lin1_w + (size_t)l * MLP_DIM * E_DIM, lin1_b + l * MLP_DIM,
            nullptr, mlp, TOK, MLP_DIM, E_DIM);
        gemm64<0><<<dim3(E_DIM / 64, TOK / 64), 256>>>(
            mlp, lin2_w + (size_t)l * E_DIM * MLP_DIM, lin2_b + l * E_DIM,
            h, tmp, TOK, E_DIM, MLP_DIM);
        ln_k<<<TOK, 256>>>(tmp, ln2_g + l * E_DIM, ln2_beta + l * E_DIM, h);
    }

    // ---- classifier head ----
    fc_k<<<N_GRAPHS, 256>>>(fc_w, fc_b, out);
}

// round 3
// speedup vs baseline: 2.1101x; 2.1101x over previous
#include <cuda_runtime.h>
#include <math.h>
#include <stdint.h>

#define N_NODES   16384
#define N_GRAPHS  64
#define NPG       256
#define F_IN      128
#define E_DIM     256
#define N_HEADS   8
#define DH        32
#define MLP_DIM   1024
#define N_LAYERS  4
#define N_CLASSES 10
#define N_EDGES   262144
#define SEQ       257                 // NODES_PER_GRAPH + 1 (cls)
#define TOK       (N_GRAPHS * SEQ)    // 16448
#define TOKP      16512               // padded to 129*128 for 128-row tiles
#define LN_EPS    1e-5f

// ---------------- scratch (static device globals, zero-initialized) --------
__device__ float g_xw [N_NODES * F_IN];
__device__ float g_gcn[N_NODES * F_IN];
__device__ float g_deg [N_NODES];
__device__ float g_dinv[N_NODES];
__device__ float g_emb[N_NODES * E_DIM];
__device__ float g_h  [TOKP * E_DIM];
__device__ float g_qkv[TOKP * 3 * E_DIM];
__device__ float g_att[TOKP * E_DIM];
__device__ float g_tmp[TOKP * E_DIM];
__device__ float g_mlp[TOKP * MLP_DIM];

// ===================== TF32 tensor-core GEMM ================================
// C[M,N] = A[M,K] * B[N,K]^T (+bias over n)(+add elementwise)(optional relu)
// Block tile 128x64x32, 8 warps (4x2), warp tile 32x32, m16n8k8 tf32 mma.
// Requires: M % 128 == 0 (buffers padded), N % 64 == 0, K % 32 == 0.
// Smem rows padded to 36 floats -> conflict-free fragment LDS.

#define SROW 36
#define AS_FLOATS (2 * 128 * SROW)
#define BS_FLOATS (2 * 64 * SROW)
#define GEMM_SMEM ((AS_FLOATS + BS_FLOATS) * 4)

__device__ __forceinline__ void mma_tf32(float* d, const float* a, const float* b) {
    asm volatile(
        "mma.sync.aligned.m16n8k8.row.col.f32.tf32.tf32.f32 "
        "{%0,%1,%2,%3}, {%4,%5,%6,%7}, {%8,%9}, {%0,%1,%2,%3};\n"
        : "+f"(d[0]), "+f"(d[1]), "+f"(d[2]), "+f"(d[3])
        : "r"(__float_as_uint(a[0])), "r"(__float_as_uint(a[1])),
          "r"(__float_as_uint(a[2])), "r"(__float_as_uint(a[3])),
          "r"(__float_as_uint(b[0])), "r"(__float_as_uint(b[1])));
}

__device__ __forceinline__ void cp16(float* dst_smem, const float* src) {
    unsigned d = (unsigned)__cvta_generic_to_shared(dst_smem);
    asm volatile("cp.async.cg.shared.global [%0], [%1], 16;\n" :: "r"(d), "l"(src));
}

template <int RELU>
__global__ __launch_bounds__(256, 2)
void gemm_tc(const float* __restrict__ A, const float* __restrict__ B,
             const float* __restrict__ bias, const float* __restrict__ add,
             float* __restrict__ C, int N, int K)
{
    extern __shared__ float sm[];
    float* As = sm;                 // [2][128][SROW]
    float* Bs = sm + AS_FLOATS;     // [2][64][SROW]

    const int tid  = threadIdx.x;
    const int warp = tid >> 5, lane = tid & 31;
    const int wm = warp >> 1, wn = warp & 1;
    const int r = lane >> 2, c = lane & 3;
    const int m0 = blockIdx.y * 128;
    const int n0 = blockIdx.x * 64;

    const int KT = K >> 5;

    float acc[2][4][4];
#pragma unroll
    for (int i = 0; i < 2; i++)
#pragma unroll
        for (int j = 0; j < 4; j++)
#pragma unroll
            for (int q = 0; q < 4; q++) acc[i][j][q] = 0.f;

    // stage loader
    auto load_stage = [&](int kt, int s) {
        const float* Ag = A + (size_t)m0 * K + kt * 32;
        const float* Bg = B + (size_t)n0 * K + kt * 32;
#pragma unroll
        for (int i = 0; i < 4; i++) {
            int idx = tid + 256 * i;
            int am = idx >> 3, ac = idx & 7;
            cp16(&As[(s * 128 + am) * SROW + ac * 4], Ag + (size_t)am * K + ac * 4);
        }
#pragma unroll
        for (int i = 0; i < 2; i++) {
            int idx = tid + 256 * i;
            int bn = idx >> 3, bc = idx & 7;
            cp16(&Bs[(s * 64 + bn) * SROW + bc * 4], Bg + (size_t)bn * K + bc * 4);
        }
    };

    load_stage(0, 0);
    asm volatile("cp.async.commit_group;\n");

    for (int kt = 0; kt < KT; kt++) {
        const int s = kt & 1;
        if (kt + 1 < KT) {
            load_stage(kt + 1, (kt + 1) & 1);
            asm volatile("cp.async.commit_group;\n");
            asm volatile("cp.async.wait_group 1;\n");
        } else {
            asm volatile("cp.async.wait_group 0;\n");
        }
        __syncthreads();

#pragma unroll
        for (int k8 = 0; k8 < 4; k8++) {
            const int kb = k8 * 8;
            float a[2][4];
#pragma unroll
            for (int ma = 0; ma < 2; ma++) {
                int mlo = s * 128 + wm * 32 + ma * 16 + r;
                a[ma][0] = As[(mlo    ) * SROW + kb + c];
                a[ma][1] = As[(mlo + 8) * SROW + kb + c];
                a[ma][2] = As[(mlo    ) * SROW + kb + c + 4];
                a[ma][3] = As[(mlo + 8) * SROW + kb + c + 4];
            }
            float b[4][2];
#pragma unroll
            for (int na = 0; na < 4; na++) {
                int nr = s * 64 + wn * 32 + na * 8 + r;
                b[na][0] = Bs[nr * SROW + kb + c];
                b[na][1] = Bs[nr * SROW + kb + c + 4];
            }
#pragma unroll
            for (int ma = 0; ma < 2; ma++)
#pragma unroll
                for (int na = 0; na < 4; na++)
                    mma_tf32(acc[ma][na], a[ma], b[na]);
        }
        __syncthreads();
    }

    // epilogue
#pragma unroll
    for (int ma = 0; ma < 2; ma++) {
        int mlo = m0 + wm * 32 + ma * 16 + r;
        int mhi = mlo + 8;
#pragma unroll
        for (int na = 0; na < 4; na++) {
            int n = n0 + wn * 32 + na * 8 + c * 2;
            float b0 = bias ? bias[n] : 0.f;
            float b1 = bias ? bias[n + 1] : 0.f;
            float v0 = acc[ma][na][0] + b0;
            float v1 = acc[ma][na][1] + b1;
            float v2 = acc[ma][na][2] + b0;
            float v3 = acc[ma][na][3] + b1;
            size_t ilo = (size_t)mlo * N + n;
            size_t ihi = (size_t)mhi * N + n;
            if (add) {
                float2 alo = *(const float2*)&add[ilo];
                float2 ahi = *(const float2*)&add[ihi];
                v0 += alo.x; v1 += alo.y; v2 += ahi.x; v3 += ahi.y;
            }
            if (RELU) {
                v0 = v0 > 0.f ? v0 : 0.f; v1 = v1 > 0.f ? v1 : 0.f;
                v2 = v2 > 0.f ? v2 : 0.f; v3 = v3 > 0.f ? v3 : 0.f;
            }
            *(float2*)&C[ilo] = make_float2(v0, v1);
            *(float2*)&C[ihi] = make_float2(v2, v3);
        }
    }
}

// ---------------- GCN pieces ----------------------------------------------
__global__ void deg_init_k() {
    int i = blockIdx.x * blockDim.x + threadIdx.x;
    if (i < N_NODES) g_deg[i] = 1.0f;
}
__global__ void deg_count_k(const int* __restrict__ ei) {
    int i = blockIdx.x * blockDim.x + threadIdx.x;
    for (; i < N_EDGES; i += gridDim.x * blockDim.x)
        atomicAdd(&g_deg[ei[N_EDGES + i]], 1.0f);
}
__global__ void dinv_k() {
    int i = blockIdx.x * blockDim.x + threadIdx.x;
    if (i < N_NODES) g_dinv[i] = rsqrtf(g_deg[i]);
}
__global__ void gcn_self_k() {
    int i = blockIdx.x * blockDim.x + threadIdx.x;
    if (i < N_NODES * F_IN) {
        int n = i >> 7;
        float d = g_dinv[n];
        g_gcn[i] = d * d * g_xw[i];
    }
}
__global__ void gcn_scatter_k(const int* __restrict__ ei) {
    int warp = (blockIdx.x * blockDim.x + threadIdx.x) >> 5;
    int lane = threadIdx.x & 31;
    int nwarp = (gridDim.x * blockDim.x) >> 5;
    for (int e = warp; e < N_EDGES; e += nwarp) {
        int row = ei[e];
        int col = ei[N_EDGES + e];
        float nm = g_dinv[row] * g_dinv[col];
        const float* src = g_xw + (size_t)row * F_IN;
        float* dst = g_gcn + (size_t)col * F_IN;
#pragma unroll
        for (int j = 0; j < 4; j++)
            atomicAdd(&dst[lane + 32 * j], nm * src[lane + 32 * j]);
    }
}
__global__ void gcn_bias_relu_k(const float* __restrict__ b) {
    int i = blockIdx.x * blockDim.x + threadIdx.x;
    if (i < N_NODES * F_IN) {
        float v = g_gcn[i] + b[i & 127];
        g_gcn[i] = v > 0.f ? v : 0.f;
    }
}

// ---------------- assemble H (cls token + embedded nodes) ------------------
__global__ void assemble_k(const float* __restrict__ cls) {
    int idx = blockIdx.x * blockDim.x + threadIdx.x;   // TOK*E_DIM exact
    int row = idx >> 8, col = idx & 255;
    int g = row / SEQ, s = row - g * SEQ;
    g_h[idx] = (s == 0) ? cls[col]
                        : g_emb[((size_t)(g * NPG + s - 1)) * E_DIM + col];
}

// ---------------- attention: one block per (graph, head) -------------------
__global__ __launch_bounds__(288)
void attn_k(const float* __restrict__ qkv, float* __restrict__ O)
{
    const int g  = blockIdx.x >> 3;
    const int hd = blockIdx.x & 7;
    __shared__ float Ks[128][DH];
    __shared__ float Vs[128][DH];

    const int tid = threadIdx.x;          // 288
    const int r = tid;
    const bool act = r < SEQ;
    const float scale = 0.17677669529663687f;   // 1/sqrt(32)

    float q[DH], acc[DH];
    float m = -1e30f, l = 0.f;
    if (act) {
        const float* qp = qkv + ((size_t)(g * SEQ + r)) * 768 + hd * DH;
#pragma unroll
        for (int d = 0; d < DH; d++) { q[d] = qp[d] * scale; acc[d] = 0.f; }
    }

    for (int c0 = 0; c0 < SEQ; c0 += 128) {
        int nk = SEQ - c0; if (nk > 128) nk = 128;
        __syncthreads();
        for (int i = tid; i < nk * DH; i += blockDim.x) {
            int kk = i >> 5, d = i & 31;
            const float* base = qkv + ((size_t)(g * SEQ + c0 + kk)) * 768
                              + E_DIM + hd * DH + d;
            Ks[kk][d] = base[0];
            Vs[kk][d] = base[E_DIM];
        }
        __syncthreads();
        if (act) {
            for (int kk = 0; kk < nk; kk++) {
                float s = 0.f;
#pragma unroll
                for (int d = 0; d < DH; d++) s += q[d] * Ks[kk][d];
                if (s <= m) {
                    float p = __expf(s - m);
                    l += p;
#pragma unroll
                    for (int d = 0; d < DH; d++) acc[d] += p * Vs[kk][d];
                } else {
                    float corr = __expf(m - s);
                    m = s;
                    l = l * corr + 1.f;
#pragma unroll
                    for (int d = 0; d < DH; d++) acc[d] = acc[d] * corr + Vs[kk][d];
                }
            }
        }
    }
    if (act) {
        float inv = 1.f / l;
        float* op = O + ((size_t)(g * SEQ + r)) * E_DIM + hd * DH;
#pragma unroll
        for (int d = 0; d < DH; d++) op[d] = acc[d] * inv;
    }
}

// ---------------- layernorm: one block (256 threads) per row ---------------
__global__ __launch_bounds__(256)
void ln_k(const float* __restrict__ in, const float* __restrict__ gam,
          const float* __restrict__ bet, float* __restrict__ out)
{
    const int row = blockIdx.x, t = threadIdx.x;
    const size_t base = (size_t)row * E_DIM;
    float v = in[base + t];

    __shared__ float red[8];
    __shared__ float bc;
    float s = v;
#pragma unroll
    for (int o = 16; o; o >>= 1) s += __shfl_xor_sync(0xffffffffu, s, o);
    if ((t & 31) == 0) red[t >> 5] = s;
    __syncthreads();
    if (t == 0) {
        float tt = 0.f;
#pragma unroll
        for (int i = 0; i < 8; i++) tt += red[i];
        bc = tt * (1.f / E_DIM);
    }
    __syncthreads();
    float mu = bc;
    float d = v - mu;
    __syncthreads();
    s = d * d;
#pragma unroll
    for (int o = 16; o; o >>= 1) s += __shfl_xor_sync(0xffffffffu, s, o);
    if ((t & 31) == 0) red[t >> 5] = s;
    __syncthreads();
    if (t == 0) {
        float tt = 0.f;
#pragma unroll
        for (int i = 0; i < 8; i++) tt += red[i];
        bc = rsqrtf(tt * (1.f / E_DIM) + LN_EPS);
    }
    __syncthreads();
    out[base + t] = d * bc * gam[t] + bet[t];
}

// ---------------- final classifier -----------------------------------------
__global__ __launch_bounds__(256)
void fc_k(const float* __restrict__ w, const float* __restrict__ b,
          float* __restrict__ out)
{
    const int g = blockIdx.x, t = threadIdx.x;
    __shared__ float hrow[E_DIM];
    hrow[t] = g_h[(size_t)g * SEQ * E_DIM + t];
    __syncthreads();
    if (t < N_CLASSES) {
        float s = b[t];
        for (int e = 0; e < E_DIM; e++) s += hrow[e] * w[t * E_DIM + e];
        out[g * N_CLASSES + t] = s;
    }
}

// ---------------------------------------------------------------------------
extern "C" void kernel_launch(void* const* d_in, const int* in_sizes, int n_in,
                              void* d_out, int out_size)
{
    const float* x        = (const float*)d_in[0];
    const int*   edge_idx = (const int*)  d_in[1];
    // d_in[2] = batch (unused: layout is arange // NPG by construction)
    const float* pos_enc  = (const float*)d_in[3];
    const float* gcn_w    = (const float*)d_in[4];
    const float* gcn_b    = (const float*)d_in[5];
    const float* cls      = (const float*)d_in[6];
    const float* emb_w    = (const float*)d_in[7];
    const float* emb_b    = (const float*)d_in[8];
    const float* in_w     = (const float*)d_in[9];
    const float* in_b     = (const float*)d_in[10];
    const float* out_w    = (const float*)d_in[11];
    const float* out_b    = (const float*)d_in[12];
    const float* lin1_w   = (const float*)d_in[13];
    const float* lin1_b   = (const float*)d_in[14];
    const float* lin2_w   = (const float*)d_in[15];
    const float* lin2_b   = (const float*)d_in[16];
    const float* ln1_g    = (const float*)d_in[17];
    const float* ln1_beta = (const float*)d_in[18];
    const float* ln2_g    = (const float*)d_in[19];
    const float* ln2_beta = (const float*)d_in[20];
    const float* fc_w     = (const float*)d_in[21];
    const float* fc_b     = (const float*)d_in[22];
    float* out = (float*)d_out;

    void *p;
    float *xw, *gcn, *emb, *h, *qkv, *att, *tmp, *mlp;
    cudaGetSymbolAddress(&p, g_xw);  xw  = (float*)p;
    cudaGetSymbolAddress(&p, g_gcn); gcn = (float*)p;
    cudaGetSymbolAddress(&p, g_emb); emb = (float*)p;
    cudaGetSymbolAddress(&p, g_h);   h   = (float*)p;
    cudaGetSymbolAddress(&p, g_qkv); qkv = (float*)p;
    cudaGetSymbolAddress(&p, g_att); att = (float*)p;
    cudaGetSymbolAddress(&p, g_tmp); tmp = (float*)p;
    cudaGetSymbolAddress(&p, g_mlp); mlp = (float*)p;

    cudaFuncSetAttribute(gemm_tc<0>, cudaFuncAttributeMaxDynamicSharedMemorySize, GEMM_SMEM);
    cudaFuncSetAttribute(gemm_tc<1>, cudaFuncAttributeMaxDynamicSharedMemorySize, GEMM_SMEM);

    // ---- GCN front-end ----
    gemm_tc<0><<<dim3(F_IN / 64, N_NODES / 128), 256, GEMM_SMEM>>>(
        x, gcn_w, nullptr, nullptr, xw, F_IN, F_IN);
    deg_init_k<<<N_NODES / 256, 256>>>();
    deg_count_k<<<512, 256>>>(edge_idx);
    dinv_k<<<N_NODES / 256, 256>>>();
    gcn_self_k<<<(N_NODES * F_IN) / 256, 256>>>();
    gcn_scatter_k<<<2048, 256>>>(edge_idx);
    gcn_bias_relu_k<<<(N_NODES * F_IN) / 256, 256>>>(gcn_b);

    // ---- embedding + pos_enc, assemble tokens ----
    gemm_tc<0><<<dim3(E_DIM / 64, N_NODES / 128), 256, GEMM_SMEM>>>(
        gcn, emb_w, emb_b, pos_enc, emb, E_DIM, F_IN);
    assemble_k<<<(TOK * E_DIM) / 256, 256>>>(cls);

    // ---- transformer layers ----
    for (int l = 0; l < N_LAYERS; l++) {
        gemm_tc<0><<<dim3(768 / 64, TOKP / 128), 256, GEMM_SMEM>>>(
            h, in_w + (size_t)l * 768 * E_DIM, in_b + l * 768,
            nullptr, qkv, 768, E_DIM);
        attn_k<<<N_GRAPHS * N_HEADS, 288>>>(qkv, att);
        gemm_tc<0><<<dim3(E_DIM / 64, TOKP / 128), 256, GEMM_SMEM>>>(
            att, out_w + (size_t)l * E_DIM * E_DIM, out_b + l * E_DIM,
            h, tmp, E_DIM, E_DIM);
        ln_k<<<TOK, 256>>>(tmp, ln1_g + l * E_DIM, ln1_beta + l * E_DIM, h);
        gemm_tc<1><<<dim3(MLP_DIM / 64, TOKP / 128), 256, GEMM_SMEM>>>(
            h, lin1_w + (size_t)l * MLP_DIM * E_DIM, lin1_b + l * MLP_DIM,
            nullptr, mlp, MLP_DIM, E_DIM);
        gemm_tc<0><<<dim3(E_DIM / 64, TOKP / 128), 256, GEMM_SMEM>>>(
            mlp, lin2_w + (size_t)l * E_DIM * MLP_DIM, lin2_b + l * E_DIM,
            h, tmp, E_DIM, MLP_DIM);
        ln_k<<<TOK, 256>>>(tmp, ln2_g + l * E_DIM, ln2_beta + l * E_DIM, h);
    }

    // ---- classifier head ----
    fc_k<<<N_GRAPHS, 256>>>(fc_w, fc_b, out);
}

// round 4
// speedup vs baseline: 2.1919x; 1.0388x over previous
#include <cuda_runtime.h>
#include <math.h>
#include <stdint.h>

#define N_NODES   16384
#define N_GRAPHS  64
#define NPG       256
#define F_IN      128
#define E_DIM     256
#define N_HEADS   8
#define DH        32
#define MLP_DIM   1024
#define N_LAYERS  4
#define N_CLASSES 10
#define N_EDGES   262144
#define SEQ       257                 // NODES_PER_GRAPH + 1 (cls)
#define TOK       (N_GRAPHS * SEQ)    // 16448
#define TOKP      16512               // padded to 129*128 for 128-row tiles
#define LN_EPS    1e-5f

// ---------------- scratch (static device globals, zero-initialized) --------
__device__ float g_xw [N_NODES * F_IN];
__device__ float g_gcn[N_NODES * F_IN];
__device__ float g_deg [N_NODES];
__device__ float g_dinv[N_NODES];
__device__ float g_emb[N_NODES * E_DIM];
__device__ float g_h  [TOKP * E_DIM];
__device__ float g_qkv[TOKP * 3 * E_DIM];
__device__ float g_att[TOKP * E_DIM];
__device__ float g_tmp[TOKP * E_DIM];
__device__ float g_mlp[TOKP * MLP_DIM];

// ===================== TF32 tensor-core GEMM ================================
// C[M,N] = A[M,K] * B[N,K]^T (+bias over n)(+add elementwise)(optional relu)
// Block tile 128x128x32, 8 warps (2x4), warp tile 64x32, m16n8k8 tf32 mma.
// Requires: M % 128 == 0 (buffers padded), N % 128 == 0, K % 32 == 0.
// Smem rows padded to 36 floats -> conflict-free fragment LDS.

#define SROW 36
#define AS_FLOATS (2 * 128 * SROW)
#define BS_FLOATS (2 * 128 * SROW)
#define GEMM_SMEM ((AS_FLOATS + BS_FLOATS) * 4)

__device__ __forceinline__ void mma_tf32(float* d, const float* a, const float* b) {
    asm volatile(
        "mma.sync.aligned.m16n8k8.row.col.f32.tf32.tf32.f32 "
        "{%0,%1,%2,%3}, {%4,%5,%6,%7}, {%8,%9}, {%0,%1,%2,%3};\n"
        : "+f"(d[0]), "+f"(d[1]), "+f"(d[2]), "+f"(d[3])
        : "r"(__float_as_uint(a[0])), "r"(__float_as_uint(a[1])),
          "r"(__float_as_uint(a[2])), "r"(__float_as_uint(a[3])),
          "r"(__float_as_uint(b[0])), "r"(__float_as_uint(b[1])));
}

__device__ __forceinline__ void cp16(float* dst_smem, const float* src) {
    unsigned d = (unsigned)__cvta_generic_to_shared(dst_smem);
    asm volatile("cp.async.cg.shared.global [%0], [%1], 16;\n" :: "r"(d), "l"(src));
}

template <int RELU>
__global__ __launch_bounds__(256, 2)
void gemm_tc(const float* __restrict__ A, const float* __restrict__ B,
             const float* __restrict__ bias, const float* __restrict__ add,
             float* __restrict__ C, int N, int K)
{
    extern __shared__ float sm[];
    float* As = sm;                 // [2][128][SROW]
    float* Bs = sm + AS_FLOATS;     // [2][128][SROW]

    const int tid  = threadIdx.x;
    const int warp = tid >> 5, lane = tid & 31;
    const int wm = warp >> 2, wn = warp & 3;     // 2 x 4 warp grid
    const int r = lane >> 2, c = lane & 3;
    const int m0 = blockIdx.y * 128;
    const int n0 = blockIdx.x * 128;

    const int KT = K >> 5;

    float acc[4][4][4];
#pragma unroll
    for (int i = 0; i < 4; i++)
#pragma unroll
        for (int j = 0; j < 4; j++)
#pragma unroll
            for (int q = 0; q < 4; q++) acc[i][j][q] = 0.f;

    // stage loader: 128 rows x 32 k for both A and B (8 float4s per thread)
    auto load_stage = [&](int kt, int s) {
        const float* Ag = A + (size_t)m0 * K + kt * 32;
        const float* Bg = B + (size_t)n0 * K + kt * 32;
#pragma unroll
        for (int i = 0; i < 4; i++) {
            int idx = tid + 256 * i;
            int am = idx >> 3, ac = idx & 7;
            cp16(&As[(s * 128 + am) * SROW + ac * 4], Ag + (size_t)am * K + ac * 4);
        }
#pragma unroll
        for (int i = 0; i < 4; i++) {
            int idx = tid + 256 * i;
            int bn = idx >> 3, bc = idx & 7;
            cp16(&Bs[(s * 128 + bn) * SROW + bc * 4], Bg + (size_t)bn * K + bc * 4);
        }
    };

    load_stage(0, 0);
    asm volatile("cp.async.commit_group;\n");

    for (int kt = 0; kt < KT; kt++) {
        const int s = kt & 1;
        if (kt + 1 < KT) {
            load_stage(kt + 1, (kt + 1) & 1);
            asm volatile("cp.async.commit_group;\n");
            asm volatile("cp.async.wait_group 1;\n");
        } else {
            asm volatile("cp.async.wait_group 0;\n");
        }
        __syncthreads();

#pragma unroll
        for (int k8 = 0; k8 < 4; k8++) {
            const int kb = k8 * 8;
            float a[4][4];
#pragma unroll
            for (int ma = 0; ma < 4; ma++) {
                int mlo = s * 128 + wm * 64 + ma * 16 + r;
                a[ma][0] = As[(mlo    ) * SROW + kb + c];
                a[ma][1] = As[(mlo + 8) * SROW + kb + c];
                a[ma][2] = As[(mlo    ) * SROW + kb + c + 4];
                a[ma][3] = As[(mlo + 8) * SROW + kb + c + 4];
            }
            float b[4][2];
#pragma unroll
            for (int na = 0; na < 4; na++) {
                int nr = s * 128 + wn * 32 + na * 8 + r;
                b[na][0] = Bs[nr * SROW + kb + c];
                b[na][1] = Bs[nr * SROW + kb + c + 4];
            }
#pragma unroll
            for (int ma = 0; ma < 4; ma++)
#pragma unroll
                for (int na = 0; na < 4; na++)
                    mma_tf32(acc[ma][na], a[ma], b[na]);
        }
        __syncthreads();
    }

    // epilogue
#pragma unroll
    for (int ma = 0; ma < 4; ma++) {
        int mlo = m0 + wm * 64 + ma * 16 + r;
        int mhi = mlo + 8;
#pragma unroll
        for (int na = 0; na < 4; na++) {
            int n = n0 + wn * 32 + na * 8 + c * 2;
            float b0 = bias ? bias[n] : 0.f;
            float b1 = bias ? bias[n + 1] : 0.f;
            float v0 = acc[ma][na][0] + b0;
            float v1 = acc[ma][na][1] + b1;
            float v2 = acc[ma][na][2] + b0;
            float v3 = acc[ma][na][3] + b1;
            size_t ilo = (size_t)mlo * N + n;
            size_t ihi = (size_t)mhi * N + n;
            if (add) {
                float2 alo = *(const float2*)&add[ilo];
                float2 ahi = *(const float2*)&add[ihi];
                v0 += alo.x; v1 += alo.y; v2 += ahi.x; v3 += ahi.y;
            }
            if (RELU) {
                v0 = v0 > 0.f ? v0 : 0.f; v1 = v1 > 0.f ? v1 : 0.f;
                v2 = v2 > 0.f ? v2 : 0.f; v3 = v3 > 0.f ? v3 : 0.f;
            }
            *(float2*)&C[ilo] = make_float2(v0, v1);
            *(float2*)&C[ihi] = make_float2(v2, v3);
        }
    }
}

// ---------------- GCN pieces ----------------------------------------------
__global__ void deg_init_k() {
    int i = blockIdx.x * blockDim.x + threadIdx.x;
    if (i < N_NODES) g_deg[i] = 1.0f;
}
__global__ void deg_count_k(const int* __restrict__ ei) {
    int i = blockIdx.x * blockDim.x + threadIdx.x;
    for (; i < N_EDGES; i += gridDim.x * blockDim.x)
        atomicAdd(&g_deg[ei[N_EDGES + i]], 1.0f);
}
__global__ void dinv_k() {
    int i = blockIdx.x * blockDim.x + threadIdx.x;
    if (i < N_NODES) g_dinv[i] = rsqrtf(g_deg[i]);
}
__global__ void gcn_self_k() {
    int i = blockIdx.x * blockDim.x + threadIdx.x;
    if (i < N_NODES * F_IN) {
        int n = i >> 7;
        float d = g_dinv[n];
        g_gcn[i] = d * d * g_xw[i];
    }
}
__global__ void gcn_scatter_k(const int* __restrict__ ei) {
    int warp = (blockIdx.x * blockDim.x + threadIdx.x) >> 5;
    int lane = threadIdx.x & 31;
    int nwarp = (gridDim.x * blockDim.x) >> 5;
    for (int e = warp; e < N_EDGES; e += nwarp) {
        int row = ei[e];
        int col = ei[N_EDGES + e];
        float nm = g_dinv[row] * g_dinv[col];
        const float* src = g_xw + (size_t)row * F_IN;
        float* dst = g_gcn + (size_t)col * F_IN;
#pragma unroll
        for (int j = 0; j < 4; j++)
            atomicAdd(&dst[lane + 32 * j], nm * src[lane + 32 * j]);
    }
}
__global__ void gcn_bias_relu_k(const float* __restrict__ b) {
    int i = blockIdx.x * blockDim.x + threadIdx.x;
    if (i < N_NODES * F_IN) {
        float v = g_gcn[i] + b[i & 127];
        g_gcn[i] = v > 0.f ? v : 0.f;
    }
}

// ---------------- assemble H (cls token + embedded nodes) ------------------
__global__ void assemble_k(const float* __restrict__ cls) {
    int idx = blockIdx.x * blockDim.x + threadIdx.x;   // TOK*E_DIM exact
    int row = idx >> 8, col = idx & 255;
    int g = row / SEQ, s = row - g * SEQ;
    g_h[idx] = (s == 0) ? cls[col]
                        : g_emb[((size_t)(g * NPG + s - 1)) * E_DIM + col];
}

// ---------------- attention: one block per (graph, head) -------------------
__global__ __launch_bounds__(288)
void attn_k(const float* __restrict__ qkv, float* __restrict__ O)
{
    const int g  = blockIdx.x >> 3;
    const int hd = blockIdx.x & 7;
    __shared__ float Ks[128][DH];
    __shared__ float Vs[128][DH];

    const int tid = threadIdx.x;          // 288
    const int r = tid;
    const bool act = r < SEQ;
    const float scale = 0.17677669529663687f;   // 1/sqrt(32)

    float q[DH], acc[DH];
    float m = -1e30f, l = 0.f;
    if (act) {
        const float* qp = qkv + ((size_t)(g * SEQ + r)) * 768 + hd * DH;
#pragma unroll
        for (int d = 0; d < DH; d++) { q[d] = qp[d] * scale; acc[d] = 0.f; }
    }

    for (int c0 = 0; c0 < SEQ; c0 += 128) {
        int nk = SEQ - c0; if (nk > 128) nk = 128;
        __syncthreads();
        for (int i = tid; i < nk * DH; i += blockDim.x) {
            int kk = i >> 5, d = i & 31;
            const float* base = qkv + ((size_t)(g * SEQ + c0 + kk)) * 768
                              + E_DIM + hd * DH + d;
            Ks[kk][d] = base[0];
            Vs[kk][d] = base[E_DIM];
        }
        __syncthreads();
        if (act) {
            for (int kk = 0; kk < nk; kk++) {
                float s = 0.f;
#pragma unroll
                for (int d = 0; d < DH; d++) s += q[d] * Ks[kk][d];
                if (s <= m) {
                    float p = __expf(s - m);
                    l += p;
#pragma unroll
                    for (int d = 0; d < DH; d++) acc[d] += p * Vs[kk][d];
                } else {
                    float corr = __expf(m - s);
                    m = s;
                    l = l * corr + 1.f;
#pragma unroll
                    for (int d = 0; d < DH; d++) acc[d] = acc[d] * corr + Vs[kk][d];
                }
            }
        }
    }
    if (act) {
        float inv = 1.f / l;
        float* op = O + ((size_t)(g * SEQ + r)) * E_DIM + hd * DH;
#pragma unroll
        for (int d = 0; d < DH; d++) op[d] = acc[d] * inv;
    }
}

// ---------------- layernorm: one block (256 threads) per row ---------------
__global__ __launch_bounds__(256)
void ln_k(const float* __restrict__ in, const float* __restrict__ gam,
          const float* __restrict__ bet, float* __restrict__ out)
{
    const int row = blockIdx.x, t = threadIdx.x;
    const size_t base = (size_t)row * E_DIM;
    float v = in[base + t];

    __shared__ float red[8];
    __shared__ float bc;
    float s = v;
#pragma unroll
    for (int o = 16; o; o >>= 1) s += __shfl_xor_sync(0xffffffffu, s, o);
    if ((t & 31) == 0) red[t >> 5] = s;
    __syncthreads();
    if (t == 0) {
        float tt = 0.f;
#pragma unroll
        for (int i = 0; i < 8; i++) tt += red[i];
        bc = tt * (1.f / E_DIM);
    }
    __syncthreads();
    float mu = bc;
    float d = v - mu;
    __syncthreads();
    s = d * d;
#pragma unroll
    for (int o = 16; o; o >>= 1) s += __shfl_xor_sync(0xffffffffu, s, o);
    if ((t & 31) == 0) red[t >> 5] = s;
    __syncthreads();
    if (t == 0) {
        float tt = 0.f;
#pragma unroll
        for (int i = 0; i < 8; i++) tt += red[i];
        bc = rsqrtf(tt * (1.f / E_DIM) + LN_EPS);
    }
    __syncthreads();
    out[base + t] = d * bc * gam[t] + bet[t];
}

// ---------------- final classifier -----------------------------------------
__global__ __launch_bounds__(256)
void fc_k(const float* __restrict__ w, const float* __restrict__ b,
          float* __restrict__ out)
{
    const int g = blockIdx.x, t = threadIdx.x;
    __shared__ float hrow[E_DIM];
    hrow[t] = g_h[(size_t)g * SEQ * E_DIM + t];
    __syncthreads();
    if (t < N_CLASSES) {
        float s = b[t];
        for (int e = 0; e < E_DIM; e++) s += hrow[e] * w[t * E_DIM + e];
        out[g * N_CLASSES + t] = s;
    }
}

// ---------------------------------------------------------------------------
extern "C" void kernel_launch(void* const* d_in, const int* in_sizes, int n_in,
                              void* d_out, int out_size)
{
    const float* x        = (const float*)d_in[0];
    const int*   edge_idx = (const int*)  d_in[1];
    // d_in[2] = batch (unused: layout is arange // NPG by construction)
    const float* pos_enc  = (const float*)d_in[3];
    const float* gcn_w    = (const float*)d_in[4];
    const float* gcn_b    = (const float*)d_in[5];
    const float* cls      = (const float*)d_in[6];
    const float* emb_w    = (const float*)d_in[7];
    const float* emb_b    = (const float*)d_in[8];
    const float* in_w     = (const float*)d_in[9];
    const float* in_b     = (const float*)d_in[10];
    const float* out_w    = (const float*)d_in[11];
    const float* out_b    = (const float*)d_in[12];
    const float* lin1_w   = (const float*)d_in[13];
    const float* lin1_b   = (const float*)d_in[14];
    const float* lin2_w   = (const float*)d_in[15];
    const float* lin2_b   = (const float*)d_in[16];
    const float* ln1_g    = (const float*)d_in[17];
    const float* ln1_beta = (const float*)d_in[18];
    const float* ln2_g    = (const float*)d_in[19];
    const float* ln2_beta = (const float*)d_in[20];
    const float* fc_w     = (const float*)d_in[21];
    const float* fc_b     = (const float*)d_in[22];
    float* out = (float*)d_out;

    void *p;
    float *xw, *gcn, *emb, *h, *qkv, *att, *tmp, *mlp;
    cudaGetSymbolAddress(&p, g_xw);  xw  = (float*)p;
    cudaGetSymbolAddress(&p, g_gcn); gcn = (float*)p;
    cudaGetSymbolAddress(&p, g_emb); emb = (float*)p;
    cudaGetSymbolAddress(&p, g_h);   h   = (float*)p;
    cudaGetSymbolAddress(&p, g_qkv); qkv = (float*)p;
    cudaGetSymbolAddress(&p, g_att); att = (float*)p;
    cudaGetSymbolAddress(&p, g_tmp); tmp = (float*)p;
    cudaGetSymbolAddress(&p, g_mlp); mlp = (float*)p;

    cudaFuncSetAttribute(gemm_tc<0>, cudaFuncAttributeMaxDynamicSharedMemorySize, GEMM_SMEM);
    cudaFuncSetAttribute(gemm_tc<1>, cudaFuncAttributeMaxDynamicSharedMemorySize, GEMM_SMEM);

    // ---- GCN front-end ----
    gemm_tc<0><<<dim3(F_IN / 128, N_NODES / 128), 256, GEMM_SMEM>>>(
        x, gcn_w, nullptr, nullptr, xw, F_IN, F_IN);
    deg_init_k<<<N_NODES / 256, 256>>>();
    deg_count_k<<<512, 256>>>(edge_idx);
    dinv_k<<<N_NODES / 256, 256>>>();
    gcn_self_k<<<(N_NODES * F_IN) / 256, 256>>>();
    gcn_scatter_k<<<2048, 256>>>(edge_idx);
    gcn_bias_relu_k<<<(N_NODES * F_IN) / 256, 256>>>(gcn_b);

    // ---- embedding + pos_enc, assemble tokens ----
    gemm_tc<0><<<dim3(E_DIM / 128, N_NODES / 128), 256, GEMM_SMEM>>>(
        gcn, emb_w, emb_b, pos_enc, emb, E_DIM, F_IN);
    assemble_k<<<(TOK * E_DIM) / 256, 256>>>(cls);

    // ---- transformer layers ----
    for (int l = 0; l < N_LAYERS; l++) {
        gemm_tc<0><<<dim3(768 / 128, TOKP / 128), 256, GEMM_SMEM>>>(
            h, in_w + (size_t)l * 768 * E_DIM, in_b + l * 768,
            nullptr, qkv, 768, E_DIM);
        attn_k<<<N_GRAPHS * N_HEADS, 288>>>(qkv, att);
        gemm_tc<0><<<dim3(E_DIM / 128, TOKP / 128), 256, GEMM_SMEM>>>(
            att, out_w + (size_t)l * E_DIM * E_DIM, out_b + l * E_DIM,
            h, tmp, E_DIM, E_DIM);
        ln_k<<<TOK, 256>>>(tmp, ln1_g + l * E_DIM, ln1_beta + l * E_DIM, h);
        gemm_tc<1><<<dim3(MLP_DIM / 128, TOKP / 128), 256, GEMM_SMEM>>>(
            h, lin1_w + (size_t)l * MLP_DIM * E_DIM, lin1_b + l * MLP_DIM,
            nullptr, mlp, MLP_DIM, E_DIM);
        gemm_tc<0><<<dim3(E_DIM / 128, TOKP / 128), 256, GEMM_SMEM>>>(
            mlp, lin2_w + (size_t)l * E_DIM * MLP_DIM, lin2_b + l * E_DIM,
            h, tmp, E_DIM, MLP_DIM);
        ln_k<<<TOK, 256>>>(tmp, ln2_g + l * E_DIM, ln2_beta + l * E_DIM, h);
    }

    // ---- classifier head ----
    fc_k<<<N_GRAPHS, 256>>>(fc_w, fc_b, out);
}

// round 5
// speedup vs baseline: 3.3817x; 1.5428x over previous
#include <cuda_runtime.h>
#include <math.h>
#include <stdint.h>

#define N_NODES   16384
#define N_GRAPHS  64
#define NPG       256
#define F_IN      128
#define E_DIM     256
#define N_HEADS   8
#define DH        32
#define MLP_DIM   1024
#define N_LAYERS  4
#define N_CLASSES 10
#define N_EDGES   262144
#define SEQ       257                 // NODES_PER_GRAPH + 1 (cls)
#define TOK       (N_GRAPHS * SEQ)    // 16448
#define TOKP      16512               // padded to 129*128 for 128-row tiles
#define LN_EPS    1e-5f

// ---------------- scratch (static device globals, zero-initialized) --------
__device__ float g_xw [N_NODES * F_IN];
__device__ float g_gcn[N_NODES * F_IN];
__device__ float g_deg [N_NODES];
__device__ float g_dinv[N_NODES];
__device__ float g_emb[N_NODES * E_DIM];
__device__ float g_h  [TOKP * E_DIM];
__device__ float g_qkv[TOKP * 3 * E_DIM];
__device__ float g_att[TOKP * E_DIM];
__device__ float g_tmp[TOKP * E_DIM];
__device__ float g_mlp[TOKP * MLP_DIM];

// ===================== TF32 tensor-core GEMM ================================
// C[M,N] = A[M,K] * B[N,K]^T (+bias over n)(+add elementwise)(optional relu)
// Block tile 128x128x32, 8 warps (2x4), warp tile 64x32, m16n8k8 tf32 mma.

#define SROW 36
#define AS_FLOATS (2 * 128 * SROW)
#define BS_FLOATS (2 * 128 * SROW)
#define GEMM_SMEM ((AS_FLOATS + BS_FLOATS) * 4)

__device__ __forceinline__ void mma_tf32(float* d, const float* a, const float* b) {
    asm volatile(
        "mma.sync.aligned.m16n8k8.row.col.f32.tf32.tf32.f32 "
        "{%0,%1,%2,%3}, {%4,%5,%6,%7}, {%8,%9}, {%0,%1,%2,%3};\n"
        : "+f"(d[0]), "+f"(d[1]), "+f"(d[2]), "+f"(d[3])
        : "r"(__float_as_uint(a[0])), "r"(__float_as_uint(a[1])),
          "r"(__float_as_uint(a[2])), "r"(__float_as_uint(a[3])),
          "r"(__float_as_uint(b[0])), "r"(__float_as_uint(b[1])));
}

__device__ __forceinline__ void cp16(float* dst_smem, const float* src) {
    unsigned d = (unsigned)__cvta_generic_to_shared(dst_smem);
    asm volatile("cp.async.cg.shared.global [%0], [%1], 16;\n" :: "r"(d), "l"(src));
}

template <int RELU>
__global__ __launch_bounds__(256, 2)
void gemm_tc(const float* __restrict__ A, const float* __restrict__ B,
             const float* __restrict__ bias, const float* __restrict__ add,
             float* __restrict__ C, int N, int K)
{
    extern __shared__ float sm[];
    float* As = sm;                 // [2][128][SROW]
    float* Bs = sm + AS_FLOATS;     // [2][128][SROW]

    const int tid  = threadIdx.x;
    const int warp = tid >> 5, lane = tid & 31;
    const int wm = warp >> 2, wn = warp & 3;     // 2 x 4 warp grid
    const int r = lane >> 2, c = lane & 3;
    const int m0 = blockIdx.y * 128;
    const int n0 = blockIdx.x * 128;

    const int KT = K >> 5;

    float acc[4][4][4];
#pragma unroll
    for (int i = 0; i < 4; i++)
#pragma unroll
        for (int j = 0; j < 4; j++)
#pragma unroll
            for (int q = 0; q < 4; q++) acc[i][j][q] = 0.f;

    auto load_stage = [&](int kt, int s) {
        const float* Ag = A + (size_t)m0 * K + kt * 32;
        const float* Bg = B + (size_t)n0 * K + kt * 32;
#pragma unroll
        for (int i = 0; i < 4; i++) {
            int idx = tid + 256 * i;
            int am = idx >> 3, ac = idx & 7;
            cp16(&As[(s * 128 + am) * SROW + ac * 4], Ag + (size_t)am * K + ac * 4);
        }
#pragma unroll
        for (int i = 0; i < 4; i++) {
            int idx = tid + 256 * i;
            int bn = idx >> 3, bc = idx & 7;
            cp16(&Bs[(s * 128 + bn) * SROW + bc * 4], Bg + (size_t)bn * K + bc * 4);
        }
    };

    load_stage(0, 0);
    asm volatile("cp.async.commit_group;\n");

    for (int kt = 0; kt < KT; kt++) {
        const int s = kt & 1;
        if (kt + 1 < KT) {
            load_stage(kt + 1, (kt + 1) & 1);
            asm volatile("cp.async.commit_group;\n");
            asm volatile("cp.async.wait_group 1;\n");
        } else {
            asm volatile("cp.async.wait_group 0;\n");
        }
        __syncthreads();

#pragma unroll
        for (int k8 = 0; k8 < 4; k8++) {
            const int kb = k8 * 8;
            float a[4][4];
#pragma unroll
            for (int ma = 0; ma < 4; ma++) {
                int mlo = s * 128 + wm * 64 + ma * 16 + r;
                a[ma][0] = As[(mlo    ) * SROW + kb + c];
                a[ma][1] = As[(mlo + 8) * SROW + kb + c];
                a[ma][2] = As[(mlo    ) * SROW + kb + c + 4];
                a[ma][3] = As[(mlo + 8) * SROW + kb + c + 4];
            }
            float b[4][2];
#pragma unroll
            for (int na = 0; na < 4; na++) {
                int nr = s * 128 + wn * 32 + na * 8 + r;
                b[na][0] = Bs[nr * SROW + kb + c];
                b[na][1] = Bs[nr * SROW + kb + c + 4];
            }
#pragma unroll
            for (int ma = 0; ma < 4; ma++)
#pragma unroll
                for (int na = 0; na < 4; na++)
                    mma_tf32(acc[ma][na], a[ma], b[na]);
        }
        __syncthreads();
    }

#pragma unroll
    for (int ma = 0; ma < 4; ma++) {
        int mlo = m0 + wm * 64 + ma * 16 + r;
        int mhi = mlo + 8;
#pragma unroll
        for (int na = 0; na < 4; na++) {
            int n = n0 + wn * 32 + na * 8 + c * 2;
            float b0 = bias ? bias[n] : 0.f;
            float b1 = bias ? bias[n + 1] : 0.f;
            float v0 = acc[ma][na][0] + b0;
            float v1 = acc[ma][na][1] + b1;
            float v2 = acc[ma][na][2] + b0;
            float v3 = acc[ma][na][3] + b1;
            size_t ilo = (size_t)mlo * N + n;
            size_t ihi = (size_t)mhi * N + n;
            if (add) {
                float2 alo = *(const float2*)&add[ilo];
                float2 ahi = *(const float2*)&add[ihi];
                v0 += alo.x; v1 += alo.y; v2 += ahi.x; v3 += ahi.y;
            }
            if (RELU) {
                v0 = v0 > 0.f ? v0 : 0.f; v1 = v1 > 0.f ? v1 : 0.f;
                v2 = v2 > 0.f ? v2 : 0.f; v3 = v3 > 0.f ? v3 : 0.f;
            }
            *(float2*)&C[ilo] = make_float2(v0, v1);
            *(float2*)&C[ihi] = make_float2(v2, v3);
        }
    }
}

// ---------------- GCN pieces ----------------------------------------------
__global__ void deg_init_k() {
    int i = blockIdx.x * blockDim.x + threadIdx.x;
    if (i < N_NODES) g_deg[i] = 1.0f;
}
__global__ void deg_count_k(const int* __restrict__ ei) {
    int i = blockIdx.x * blockDim.x + threadIdx.x;
    for (; i < N_EDGES; i += gridDim.x * blockDim.x)
        atomicAdd(&g_deg[ei[N_EDGES + i]], 1.0f);
}
__global__ void dinv_k() {
    int i = blockIdx.x * blockDim.x + threadIdx.x;
    if (i < N_NODES) g_dinv[i] = rsqrtf(g_deg[i]);
}
__global__ void gcn_self_k() {
    int i = blockIdx.x * blockDim.x + threadIdx.x;
    if (i < N_NODES * F_IN) {
        int n = i >> 7;
        float d = g_dinv[n];
        g_gcn[i] = d * d * g_xw[i];
    }
}
__global__ void gcn_scatter_k(const int* __restrict__ ei) {
    int warp = (blockIdx.x * blockDim.x + threadIdx.x) >> 5;
    int lane = threadIdx.x & 31;
    int nwarp = (gridDim.x * blockDim.x) >> 5;
    for (int e = warp; e < N_EDGES; e += nwarp) {
        int row = ei[e];
        int col = ei[N_EDGES + e];
        float nm = g_dinv[row] * g_dinv[col];
        const float* src = g_xw + (size_t)row * F_IN;
        float* dst = g_gcn + (size_t)col * F_IN;
#pragma unroll
        for (int j = 0; j < 4; j++)
            atomicAdd(&dst[lane + 32 * j], nm * src[lane + 32 * j]);
    }
}
__global__ void gcn_bias_relu_k(const float* __restrict__ b) {
    int i = blockIdx.x * blockDim.x + threadIdx.x;
    if (i < N_NODES * F_IN) {
        float v = g_gcn[i] + b[i & 127];
        g_gcn[i] = v > 0.f ? v : 0.f;
    }
}

// ---------------- assemble H (cls token + embedded nodes) ------------------
__global__ void assemble_k(const float* __restrict__ cls) {
    int idx = blockIdx.x * blockDim.x + threadIdx.x;   // TOK*E_DIM exact
    int row = idx >> 8, col = idx & 255;
    int g = row / SEQ, s = row - g * SEQ;
    g_h[idx] = (s == 0) ? cls[col]
                        : g_emb[((size_t)(g * NPG + s - 1)) * E_DIM + col];
}

// ============== tensor-core flash attention: block per (graph, head) =======
// K in smem [264][36], V^T in smem [32][268]; warps own 16-row Q tiles;
// online softmax with c-frag -> a-frag shuffle permutation.
#define SEQP 264
#define KSTR 36
#define VSTR 268
#define ATTN_SMEM ((SEQP * KSTR + 32 * VSTR) * 4)

__global__ __launch_bounds__(256)
void attn_tc_k(const float* __restrict__ qkv, float* __restrict__ O)
{
    const int g  = blockIdx.x >> 3;
    const int hd = blockIdx.x & 7;
    extern __shared__ float smA[];
    float* Ks = smA;                    // [SEQP][KSTR]
    float* Vt = smA + SEQP * KSTR;      // [32][VSTR]

    const int tid = threadIdx.x, warp = tid >> 5, lane = tid & 31;
    const int r = lane >> 2, c = lane & 3;
    const float scale = 0.17677669529663687f;   // 1/sqrt(32)
    const unsigned FULL = 0xffffffffu;

    // ---- load K and V^T (pad keys >= SEQ with zeros) ----
    for (int i = tid; i < SEQP * 32; i += 256) {
        int key = i >> 5, d = i & 31;
        float kv = 0.f, vv = 0.f;
        if (key < SEQ) {
            const float* p = qkv + ((size_t)(g * SEQ + key)) * 768 + E_DIM + hd * DH + d;
            kv = p[0]; vv = p[E_DIM];
        }
        Ks[key * KSTR + d] = kv;
        Vt[d * VSTR + key] = vv;
    }
    __syncthreads();

    // ---- q tiles of 16 rows: ceil(257/16)=17 tiles, warp-strided ----
    for (int qt = warp; qt < 17; qt += 8) {
        const int q0 = qt * 16;
        int row0 = q0 + r;      if (row0 > 256) row0 = 256;
        int row1 = q0 + r + 8;  if (row1 > 256) row1 = 256;
        const float* Q0 = qkv + ((size_t)(g * SEQ + row0)) * 768 + hd * DH;
        const float* Q1 = qkv + ((size_t)(g * SEQ + row1)) * 768 + hd * DH;

        float qa[4][4];
#pragma unroll
        for (int ks = 0; ks < 4; ks++) {
            qa[ks][0] = Q0[ks * 8 + c]     * scale;
            qa[ks][1] = Q1[ks * 8 + c]     * scale;
            qa[ks][2] = Q0[ks * 8 + c + 4] * scale;
            qa[ks][3] = Q1[ks * 8 + c + 4] * scale;
        }

        float m0 = -1e30f, m1 = -1e30f, l0 = 0.f, l1 = 0.f;
        float oa[4][4];
#pragma unroll
        for (int nc = 0; nc < 4; nc++)
#pragma unroll
            for (int q = 0; q < 4; q++) oa[nc][q] = 0.f;

        for (int n0 = 0; n0 < SEQP; n0 += 8) {
            // ---- scores S = Q K^T for this 8-key chunk ----
            float s[4] = {0.f, 0.f, 0.f, 0.f};
#pragma unroll
            for (int ks = 0; ks < 4; ks++) {
                float b[2];
                b[0] = Ks[(n0 + r) * KSTR + ks * 8 + c];
                b[1] = Ks[(n0 + r) * KSTR + ks * 8 + c + 4];
                mma_tf32(s, qa[ks], b);
            }
            // mask padded key columns
            int col = n0 + 2 * c;
            if (col     >= SEQ) { s[0] = -1e30f; s[2] = -1e30f; }
            if (col + 1 >= SEQ) { s[1] = -1e30f; s[3] = -1e30f; }

            // ---- online softmax (rows r and r+8) ----
            float cm0 = fmaxf(s[0], s[1]);
            float cm1 = fmaxf(s[2], s[3]);
            cm0 = fmaxf(cm0, __shfl_xor_sync(FULL, cm0, 1));
            cm0 = fmaxf(cm0, __shfl_xor_sync(FULL, cm0, 2));
            cm1 = fmaxf(cm1, __shfl_xor_sync(FULL, cm1, 1));
            cm1 = fmaxf(cm1, __shfl_xor_sync(FULL, cm1, 2));
            float nm0 = fmaxf(m0, cm0), nm1 = fmaxf(m1, cm1);
            float al0 = __expf(m0 - nm0), al1 = __expf(m1 - nm1);
            m0 = nm0; m1 = nm1;
            float p0 = __expf(s[0] - nm0), p1 = __expf(s[1] - nm0);
            float p2 = __expf(s[2] - nm1), p3 = __expf(s[3] - nm1);
            float rs0 = p0 + p1, rs1 = p2 + p3;
            rs0 += __shfl_xor_sync(FULL, rs0, 1);
            rs0 += __shfl_xor_sync(FULL, rs0, 2);
            rs1 += __shfl_xor_sync(FULL, rs1, 1);
            rs1 += __shfl_xor_sync(FULL, rs1, 2);
            l0 = l0 * al0 + rs0;
            l1 = l1 * al1 + rs1;
#pragma unroll
            for (int nc = 0; nc < 4; nc++) {
                oa[nc][0] *= al0; oa[nc][1] *= al0;
                oa[nc][2] *= al1; oa[nc][3] *= al1;
            }

            // ---- P c-frag -> a-frag permutation via shuffles ----
            int src0 = (lane & ~3) | (c >> 1);
            int src1 = src0 + 2;
            float q00 = __shfl_sync(FULL, p0, src0), q01 = __shfl_sync(FULL, p1, src0);
            float q20 = __shfl_sync(FULL, p2, src0), q21 = __shfl_sync(FULL, p3, src0);
            float q02 = __shfl_sync(FULL, p0, src1), q03 = __shfl_sync(FULL, p1, src1);
            float q22 = __shfl_sync(FULL, p2, src1), q23 = __shfl_sync(FULL, p3, src1);
            float pa[4];
            pa[0] = (c & 1) ? q01 : q00;   // P[r][c]
            pa[1] = (c & 1) ? q21 : q20;   // P[r+8][c]
            pa[2] = (c & 1) ? q03 : q02;   // P[r][c+4]
            pa[3] = (c & 1) ? q23 : q22;   // P[r+8][c+4]

            // ---- O += P V ----
#pragma unroll
            for (int nc = 0; nc < 4; nc++) {
                float b[2];
                b[0] = Vt[(nc * 8 + r) * VSTR + n0 + c];
                b[1] = Vt[(nc * 8 + r) * VSTR + n0 + c + 4];
                mma_tf32(oa[nc], pa, b);
            }
        }

        // ---- normalize and store ----
        float inv0 = 1.f / l0, inv1 = 1.f / l1;
        int orow0 = q0 + r, orow1 = q0 + r + 8;
#pragma unroll
        for (int nc = 0; nc < 4; nc++) {
            int col = hd * DH + nc * 8 + 2 * c;
            if (orow0 < SEQ) {
                float* op = O + ((size_t)(g * SEQ + orow0)) * E_DIM + col;
                op[0] = oa[nc][0] * inv0;
                op[1] = oa[nc][1] * inv0;
            }
            if (orow1 < SEQ) {
                float* op = O + ((size_t)(g * SEQ + orow1)) * E_DIM + col;
                op[0] = oa[nc][2] * inv1;
                op[1] = oa[nc][3] * inv1;
            }
        }
    }
}

// ---------------- layernorm: one block (256 threads) per row ---------------
__global__ __launch_bounds__(256)
void ln_k(const float* __restrict__ in, const float* __restrict__ gam,
          const float* __restrict__ bet, float* __restrict__ out)
{
    const int row = blockIdx.x, t = threadIdx.x;
    const size_t base = (size_t)row * E_DIM;
    float v = in[base + t];

    __shared__ float red[8];
    __shared__ float bc;
    float s = v;
#pragma unroll
    for (int o = 16; o; o >>= 1) s += __shfl_xor_sync(0xffffffffu, s, o);
    if ((t & 31) == 0) red[t >> 5] = s;
    __syncthreads();
    if (t == 0) {
        float tt = 0.f;
#pragma unroll
        for (int i = 0; i < 8; i++) tt += red[i];
        bc = tt * (1.f / E_DIM);
    }
    __syncthreads();
    float mu = bc;
    float d = v - mu;
    __syncthreads();
    s = d * d;
#pragma unroll
    for (int o = 16; o; o >>= 1) s += __shfl_xor_sync(0xffffffffu, s, o);
    if ((t & 31) == 0) red[t >> 5] = s;
    __syncthreads();
    if (t == 0) {
        float tt = 0.f;
#pragma unroll
        for (int i = 0; i < 8; i++) tt += red[i];
        bc = rsqrtf(tt * (1.f / E_DIM) + LN_EPS);
    }
    __syncthreads();
    out[base + t] = d * bc * gam[t] + bet[t];
}

// ---------------- final classifier -----------------------------------------
__global__ __launch_bounds__(256)
void fc_k(const float* __restrict__ w, const float* __restrict__ b,
          float* __restrict__ out)
{
    const int g = blockIdx.x, t = threadIdx.x;
    __shared__ float hrow[E_DIM];
    hrow[t] = g_h[(size_t)g * SEQ * E_DIM + t];
    __syncthreads();
    if (t < N_CLASSES) {
        float s = b[t];
        for (int e = 0; e < E_DIM; e++) s += hrow[e] * w[t * E_DIM + e];
        out[g * N_CLASSES + t] = s;
    }
}

// ---------------------------------------------------------------------------
extern "C" void kernel_launch(void* const* d_in, const int* in_sizes, int n_in,
                              void* d_out, int out_size)
{
    const float* x        = (const float*)d_in[0];
    const int*   edge_idx = (const int*)  d_in[1];
    // d_in[2] = batch (unused: layout is arange // NPG by construction)
    const float* pos_enc  = (const float*)d_in[3];
    const float* gcn_w    = (const float*)d_in[4];
    const float* gcn_b    = (const float*)d_in[5];
    const float* cls      = (const float*)d_in[6];
    const float* emb_w    = (const float*)d_in[7];
    const float* emb_b    = (const float*)d_in[8];
    const float* in_w     = (const float*)d_in[9];
    const float* in_b     = (const float*)d_in[10];
    const float* out_w    = (const float*)d_in[11];
    const float* out_b    = (const float*)d_in[12];
    const float* lin1_w   = (const float*)d_in[13];
    const float* lin1_b   = (const float*)d_in[14];
    const float* lin2_w   = (const float*)d_in[15];
    const float* lin2_b   = (const float*)d_in[16];
    const float* ln1_g    = (const float*)d_in[17];
    const float* ln1_beta = (const float*)d_in[18];
    const float* ln2_g    = (const float*)d_in[19];
    const float* ln2_beta = (const float*)d_in[20];
    const float* fc_w     = (const float*)d_in[21];
    const float* fc_b     = (const float*)d_in[22];
    float* out = (float*)d_out;

    void *p;
    float *xw, *gcn, *emb, *h, *qkv, *att, *tmp, *mlp;
    cudaGetSymbolAddress(&p, g_xw);  xw  = (float*)p;
    cudaGetSymbolAddress(&p, g_gcn); gcn = (float*)p;
    cudaGetSymbolAddress(&p, g_emb); emb = (float*)p;
    cudaGetSymbolAddress(&p, g_h);   h   = (float*)p;
    cudaGetSymbolAddress(&p, g_qkv); qkv = (float*)p;
    cudaGetSymbolAddress(&p, g_att); att = (float*)p;
    cudaGetSymbolAddress(&p, g_tmp); tmp = (float*)p;
    cudaGetSymbolAddress(&p, g_mlp); mlp = (float*)p;

    cudaFuncSetAttribute(gemm_tc<0>, cudaFuncAttributeMaxDynamicSharedMemorySize, GEMM_SMEM);
    cudaFuncSetAttribute(gemm_tc<1>, cudaFuncAttributeMaxDynamicSharedMemorySize, GEMM_SMEM);
    cudaFuncSetAttribute(attn_tc_k, cudaFuncAttributeMaxDynamicSharedMemorySize, ATTN_SMEM);

    // ---- GCN front-end (deg chain first so ncu -s 5 lands on gemm_tc) ----
    deg_init_k<<<N_NODES / 256, 256>>>();                               // 0
    deg_count_k<<<512, 256>>>(edge_idx);                                // 1
    dinv_k<<<N_NODES / 256, 256>>>();                                   // 2
    gemm_tc<0><<<dim3(F_IN / 128, N_NODES / 128), 256, GEMM_SMEM>>>(    // 3
        x, gcn_w, nullptr, nullptr, xw, F_IN, F_IN);
    gcn_self_k<<<(N_NODES * F_IN) / 256, 256>>>();
    gcn_scatter_k<<<2048, 256>>>(edge_idx);
    gcn_bias_relu_k<<<(N_NODES * F_IN) / 256, 256>>>(gcn_b);

    // ---- embedding + pos_enc, assemble tokens ----
    gemm_tc<0><<<dim3(E_DIM / 128, N_NODES / 128), 256, GEMM_SMEM>>>(
        gcn, emb_w, emb_b, pos_enc, emb, E_DIM, F_IN);
    assemble_k<<<(TOK * E_DIM) / 256, 256>>>(cls);

    // ---- transformer layers ----
    for (int l = 0; l < N_LAYERS; l++) {
        gemm_tc<0><<<dim3(768 / 128, TOKP / 128), 256, GEMM_SMEM>>>(
            h, in_w + (size_t)l * 768 * E_DIM, in_b + l * 768,
            nullptr, qkv, 768, E_DIM);
        attn_tc_k<<<N_GRAPHS * N_HEADS, 256, ATTN_SMEM>>>(qkv, att);
        gemm_tc<0><<<dim3(E_DIM / 128, TOKP / 128), 256, GEMM_SMEM>>>(
            att, out_w + (size_t)l * E_DIM * E_DIM, out_b + l * E_DIM,
            h, tmp, E_DIM, E_DIM);
        ln_k<<<TOK, 256>>>(tmp, ln1_g + l * E_DIM, ln1_beta + l * E_DIM, h);
        gemm_tc<1><<<dim3(MLP_DIM / 128, TOKP / 128), 256, GEMM_SMEM>>>(
            h, lin1_w + (size_t)l * MLP_DIM * E_DIM, lin1_b + l * MLP_DIM,
            nullptr, mlp, MLP_DIM, E_DIM);
        gemm_tc<0><<<dim3(E_DIM / 128, TOKP / 128), 256, GEMM_SMEM>>>(
            mlp, lin2_w + (size_t)l * E_DIM * MLP_DIM, lin2_b + l * E_DIM,
            h, tmp, E_DIM, MLP_DIM);
        ln_k<<<TOK, 256>>>(tmp, ln2_g + l * E_DIM, ln2_beta + l * E_DIM, h);
    }

    // ---- classifier head ----
    fc_k<<<N_GRAPHS, 256>>>(fc_w, fc_b, out);
}

// round 8
// speedup vs baseline: 4.2080x; 1.2443x over previous
#include <cuda_runtime.h>
#include <cuda_fp16.h>
#include <math.h>
#include <stdint.h>

#define N_NODES   16384
#define N_GRAPHS  64
#define NPG       256
#define F_IN      128
#define E_DIM     256
#define N_HEADS   8
#define DH        32
#define MLP_DIM   1024
#define N_LAYERS  4
#define N_CLASSES 10
#define N_EDGES   262144
#define SEQ       257                 // NODES_PER_GRAPH + 1 (cls)
#define TOK       (N_GRAPHS * SEQ)    // 16448
#define TOKP      16512               // padded to 129*128 for 128-row tiles
#define LN_EPS    1e-5f

// ---------------- scratch (static device globals, zero-initialized) --------
__device__ float g_xw [N_NODES * F_IN];
__device__ float g_gcn[N_NODES * F_IN];
__device__ float g_deg [N_NODES];
__device__ float g_dinv[N_NODES];
__device__ float g_emb[N_NODES * E_DIM];
__device__ float g_h  [TOKP * E_DIM];
__device__ float g_qkv[TOKP * 3 * E_DIM];
__device__ float g_tmp[TOKP * E_DIM];

// fp16 operand mirrors
__device__ __half g_x16  [N_NODES * F_IN];
__device__ __half g_gcnw16[F_IN * F_IN];
__device__ __half g_gcn16[N_NODES * F_IN];
__device__ __half g_embw16[E_DIM * F_IN];
__device__ __half g_h16  [TOKP * E_DIM];
__device__ __half g_att16[TOKP * E_DIM];
__device__ __half g_mlp16[TOKP * MLP_DIM];
__device__ __half g_inw16 [N_LAYERS * 3 * E_DIM * E_DIM];
__device__ __half g_outw16[N_LAYERS * E_DIM * E_DIM];
__device__ __half g_l1w16 [N_LAYERS * MLP_DIM * E_DIM];
__device__ __half g_l2w16 [N_LAYERS * E_DIM * MLP_DIM];

// ===================== helpers =============================================
__device__ __forceinline__ uint32_t smem_u32(const void* p) {
    return (uint32_t)__cvta_generic_to_shared(p);
}
__device__ __forceinline__ void cp16s(uint32_t dst, const void* src) {
    asm volatile("cp.async.cg.shared.global [%0], [%1], 16;\n" :: "r"(dst), "l"(src));
}
#define CP_COMMIT() asm volatile("cp.async.commit_group;\n")

__device__ __forceinline__ void mma_f16(float* d, const uint32_t* a, const uint32_t* b) {
    asm volatile(
        "mma.sync.aligned.m16n8k16.row.col.f32.f16.f16.f32 "
        "{%0,%1,%2,%3}, {%4,%5,%6,%7}, {%8,%9}, {%0,%1,%2,%3};\n"
        : "+f"(d[0]), "+f"(d[1]), "+f"(d[2]), "+f"(d[3])
        : "r"(a[0]), "r"(a[1]), "r"(a[2]), "r"(a[3]), "r"(b[0]), "r"(b[1]));
}

// ===================== fp16 HMMA GEMM =======================================
// C[M,N] = A[M,K] * B[N,K]^T (+bias over n)(+add fp32)(relu); A,B fp16.
// Block 128x128x32, 8 warps (2x4), warp tile 64x32, m16n8k16.
// Smem stage: 128 rows x 32 halves, stride 40 halves (80B) -> conflict-free
// ldmatrix (20*row mod 32 distinct) and B LDS.32.
#define HROW 40
#define STG  (128 * HROW)               // halves per matrix per stage
#define GH_SMEM (4 * STG * 2)           // 2 stages x (A+B) x 2 bytes = 40960

template <int RELU>
__global__ __launch_bounds__(256, 2)
void gemm_h(const __half* __restrict__ A, const __half* __restrict__ B,
            const float* __restrict__ bias, const float* __restrict__ add,
            float* __restrict__ C32, __half* __restrict__ C16, int N, int K)
{
    extern __shared__ __half smh[];
    __half* As = smh;            // [2][STG]
    __half* Bs = smh + 2 * STG;  // [2][STG]

    const int tid = threadIdx.x;
    const int warp = tid >> 5, lane = tid & 31;
    const int wm = warp >> 2, wn = warp & 3;     // 2 x 4 warp grid
    const int r = lane >> 2, c = lane & 3;
    const int m0 = blockIdx.y * 128;
    const int n0 = blockIdx.x * 128;
    const int KT = K >> 5;

    float acc[4][4][4];
#pragma unroll
    for (int i = 0; i < 4; i++)
#pragma unroll
        for (int j = 0; j < 4; j++)
#pragma unroll
            for (int q = 0; q < 4; q++) acc[i][j][q] = 0.f;

    // stage loader: 512 16B-chunks per matrix, 2 per thread per matrix
    auto load_stage = [&](int kt, int s) {
        const __half* Ag = A + (size_t)m0 * K + kt * 32;
        const __half* Bg = B + (size_t)n0 * K + kt * 32;
        const uint32_t sa = smem_u32(&As[s * STG]);
        const uint32_t sb = smem_u32(&Bs[s * STG]);
#pragma unroll
        for (int i = 0; i < 2; i++) {
            int id = tid + 256 * i;
            int row = id >> 2, ch = id & 3;
            cp16s(sa + row * 80 + ch * 16, Ag + (size_t)row * K + ch * 8);
            cp16s(sb + row * 80 + ch * 16, Bg + (size_t)row * K + ch * 8);
        }
    };

    load_stage(0, 0);
    CP_COMMIT();

    for (int kt = 0; kt < KT; kt++) {
        const int s = kt & 1;
        if (kt + 1 < KT) {
            load_stage(kt + 1, s ^ 1);
            CP_COMMIT();
            asm volatile("cp.async.wait_group 1;\n");
        } else {
            asm volatile("cp.async.wait_group 0;\n");
        }
        __syncthreads();

        const uint32_t saBase = smem_u32(&As[s * STG]);
        const __half* Bst = &Bs[s * STG];
#pragma unroll
        for (int ks = 0; ks < 2; ks++) {
            uint32_t a[4][4];
#pragma unroll
            for (int ma = 0; ma < 4; ma++) {
                int mbase = wm * 64 + ma * 16;
                uint32_t addr = saBase + (mbase + (lane & 15)) * 80
                              + ks * 32 + ((lane >> 4) & 1) * 16;
                asm volatile(
                    "ldmatrix.sync.aligned.m8n8.x4.shared.b16 {%0,%1,%2,%3}, [%4];"
                    : "=r"(a[ma][0]), "=r"(a[ma][1]), "=r"(a[ma][2]), "=r"(a[ma][3])
                    : "r"(addr));
            }
            uint32_t b[4][2];
#pragma unroll
            for (int na = 0; na < 4; na++) {
                int n = wn * 32 + na * 8 + r;
                const __half* bp = Bst + n * HROW + ks * 16 + c * 2;
                b[na][0] = *(const uint32_t*)(bp);
                b[na][1] = *(const uint32_t*)(bp + 8);
            }
#pragma unroll
            for (int ma = 0; ma < 4; ma++)
#pragma unroll
                for (int na = 0; na < 4; na++)
                    mma_f16(acc[ma][na], a[ma], b[na]);
        }
        __syncthreads();
    }

    // epilogue: direct stores from c-frags
#pragma unroll
    for (int ma = 0; ma < 4; ma++) {
        int mlo = m0 + wm * 64 + ma * 16 + r;
        int mhi = mlo + 8;
#pragma unroll
        for (int na = 0; na < 4; na++) {
            int n = n0 + wn * 32 + na * 8 + c * 2;
            float b0 = bias ? bias[n] : 0.f;
            float b1 = bias ? bias[n + 1] : 0.f;
            float v0 = acc[ma][na][0] + b0;
            float v1 = acc[ma][na][1] + b1;
            float v2 = acc[ma][na][2] + b0;
            float v3 = acc[ma][na][3] + b1;
            size_t ilo = (size_t)mlo * N + n;
            size_t ihi = (size_t)mhi * N + n;
            if (add) {
                float2 alo = *(const float2*)&add[ilo];
                float2 ahi = *(const float2*)&add[ihi];
                v0 += alo.x; v1 += alo.y; v2 += ahi.x; v3 += ahi.y;
            }
            if (RELU) {
                v0 = v0 > 0.f ? v0 : 0.f; v1 = v1 > 0.f ? v1 : 0.f;
                v2 = v2 > 0.f ? v2 : 0.f; v3 = v3 > 0.f ? v3 : 0.f;
            }
            if (C32) {
                *(float2*)&C32[ilo] = make_float2(v0, v1);
                *(float2*)&C32[ihi] = make_float2(v2, v3);
            }
            if (C16) {
                *(__half2*)&C16[ilo] = __floats2half2_rn(v0, v1);
                *(__half2*)&C16[ihi] = __floats2half2_rn(v2, v3);
            }
        }
    }
}

// ---------------- fp32 -> fp16 convert -------------------------------------
__global__ void cvt_k(const float* __restrict__ s, __half* __restrict__ d, int n) {
    int i = blockIdx.x * blockDim.x + threadIdx.x;
    if (i < n) d[i] = __float2half_rn(s[i]);
}

// ---------------- GCN pieces ----------------------------------------------
__global__ void deg_init_k() {
    int i = blockIdx.x * blockDim.x + threadIdx.x;
    if (i < N_NODES) g_deg[i] = 1.0f;
}
__global__ void deg_count_k(const int* __restrict__ ei) {
    int i = blockIdx.x * blockDim.x + threadIdx.x;
    for (; i < N_EDGES; i += gridDim.x * blockDim.x)
        atomicAdd(&g_deg[ei[N_EDGES + i]], 1.0f);
}
__global__ void dinv_k() {
    int i = blockIdx.x * blockDim.x + threadIdx.x;
    if (i < N_NODES) g_dinv[i] = rsqrtf(g_deg[i]);
}
__global__ void gcn_self_k() {
    int i = blockIdx.x * blockDim.x + threadIdx.x;
    if (i < N_NODES * F_IN) {
        int n = i >> 7;
        float d = g_dinv[n];
        g_gcn[i] = d * d * g_xw[i];
    }
}
__global__ void gcn_scatter_k(const int* __restrict__ ei) {
    int warp = (blockIdx.x * blockDim.x + threadIdx.x) >> 5;
    int lane = threadIdx.x & 31;
    int nwarp = (gridDim.x * blockDim.x) >> 5;
    for (int e = warp; e < N_EDGES; e += nwarp) {
        int row = ei[e];
        int col = ei[N_EDGES + e];
        float nm = g_dinv[row] * g_dinv[col];
        const float* src = g_xw + (size_t)row * F_IN;
        float* dst = g_gcn + (size_t)col * F_IN;
#pragma unroll
        for (int j = 0; j < 4; j++)
            atomicAdd(&dst[lane + 32 * j], nm * src[lane + 32 * j]);
    }
}
__global__ void gcn_bias_relu_k(const float* __restrict__ b) {
    int i = blockIdx.x * blockDim.x + threadIdx.x;
    if (i < N_NODES * F_IN) {
        float v = g_gcn[i] + b[i & 127];
        g_gcn16[i] = __float2half_rn(v > 0.f ? v : 0.f);
    }
}

// ---------------- assemble H (cls token + embedded nodes) ------------------
__global__ void assemble_k(const float* __restrict__ cls) {
    int idx = blockIdx.x * blockDim.x + threadIdx.x;   // TOK*E_DIM exact
    int row = idx >> 8, col = idx & 255;
    int g = row / SEQ, s = row - g * SEQ;
    float v = (s == 0) ? cls[col]
                       : g_emb[((size_t)(g * NPG + s - 1)) * E_DIM + col];
    g_h[idx] = v;
    g_h16[idx] = __float2half_rn(v);
}

// ============== tensor-core flash attention (tf32 HMMA) =====================
__device__ __forceinline__ void mma_tf32(float* d, const float* a, const float* b) {
    asm volatile(
        "mma.sync.aligned.m16n8k8.row.col.f32.tf32.tf32.f32 "
        "{%0,%1,%2,%3}, {%4,%5,%6,%7}, {%8,%9}, {%0,%1,%2,%3};\n"
        : "+f"(d[0]), "+f"(d[1]), "+f"(d[2]), "+f"(d[3])
        : "r"(__float_as_uint(a[0])), "r"(__float_as_uint(a[1])),
          "r"(__float_as_uint(a[2])), "r"(__float_as_uint(a[3])),
          "r"(__float_as_uint(b[0])), "r"(__float_as_uint(b[1])));
}

#define SEQP 264
#define KSTR 36
#define VSTR 268
#define ATTN_SMEM ((SEQP * KSTR + 32 * VSTR) * 4)

__global__ __launch_bounds__(256)
void attn_tc_k(const float* __restrict__ qkv, __half* __restrict__ O)
{
    const int g  = blockIdx.x >> 3;
    const int hd = blockIdx.x & 7;
    extern __shared__ float smA[];
    float* Ks = smA;                    // [SEQP][KSTR]
    float* Vt = smA + SEQP * KSTR;      // [32][VSTR]

    const int tid = threadIdx.x, warp = tid >> 5, lane = tid & 31;
    const int r = lane >> 2, c = lane & 3;
    const float scale = 0.17677669529663687f;   // 1/sqrt(32)
    const unsigned FULL = 0xffffffffu;

    for (int i = tid; i < SEQP * 32; i += 256) {
        int key = i >> 5, d = i & 31;
        float kv = 0.f, vv = 0.f;
        if (key < SEQ) {
            const float* p = qkv + ((size_t)(g * SEQ + key)) * 768 + E_DIM + hd * DH + d;
            kv = p[0]; vv = p[E_DIM];
        }
        Ks[key * KSTR + d] = kv;
        Vt[d * VSTR + key] = vv;
    }
    __syncthreads();

    for (int qt = warp; qt < 17; qt += 8) {
        const int q0 = qt * 16;
        int row0 = q0 + r;      if (row0 > 256) row0 = 256;
        int row1 = q0 + r + 8;  if (row1 > 256) row1 = 256;
        const float* Q0 = qkv + ((size_t)(g * SEQ + row0)) * 768 + hd * DH;
        const float* Q1 = qkv + ((size_t)(g * SEQ + row1)) * 768 + hd * DH;

        float qa[4][4];
#pragma unroll
        for (int ks = 0; ks < 4; ks++) {
            qa[ks][0] = Q0[ks * 8 + c]     * scale;
            qa[ks][1] = Q1[ks * 8 + c]     * scale;
            qa[ks][2] = Q0[ks * 8 + c + 4] * scale;
            qa[ks][3] = Q1[ks * 8 + c + 4] * scale;
        }

        float m0 = -1e30f, m1 = -1e30f, l0 = 0.f, l1 = 0.f;
        float oa[4][4];
#pragma unroll
        for (int nc = 0; nc < 4; nc++)
#pragma unroll
            for (int q = 0; q < 4; q++) oa[nc][q] = 0.f;

        for (int n0 = 0; n0 < SEQP; n0 += 8) {
            float s[4] = {0.f, 0.f, 0.f, 0.f};
#pragma unroll
            for (int ks = 0; ks < 4; ks++) {
                float b[2];
                b[0] = Ks[(n0 + r) * KSTR + ks * 8 + c];
                b[1] = Ks[(n0 + r) * KSTR + ks * 8 + c + 4];
                mma_tf32(s, qa[ks], b);
            }
            int col = n0 + 2 * c;
            if (col     >= SEQ) { s[0] = -1e30f; s[2] = -1e30f; }
            if (col + 1 >= SEQ) { s[1] = -1e30f; s[3] = -1e30f; }

            float cm0 = fmaxf(s[0], s[1]);
            float cm1 = fmaxf(s[2], s[3]);
            cm0 = fmaxf(cm0, __shfl_xor_sync(FULL, cm0, 1));
            cm0 = fmaxf(cm0, __shfl_xor_sync(FULL, cm0, 2));
            cm1 = fmaxf(cm1, __shfl_xor_sync(FULL, cm1, 1));
            cm1 = fmaxf(cm1, __shfl_xor_sync(FULL, cm1, 2));
            float nm0 = fmaxf(m0, cm0), nm1 = fmaxf(m1, cm1);
            float al0 = __expf(m0 - nm0), al1 = __expf(m1 - nm1);
            m0 = nm0; m1 = nm1;
            float p0 = __expf(s[0] - nm0), p1 = __expf(s[1] - nm0);
            float p2 = __expf(s[2] - nm1), p3 = __expf(s[3] - nm1);
            float rs0 = p0 + p1, rs1 = p2 + p3;
            rs0 += __shfl_xor_sync(FULL, rs0, 1);
            rs0 += __shfl_xor_sync(FULL, rs0, 2);
            rs1 += __shfl_xor_sync(FULL, rs1, 1);
            rs1 += __shfl_xor_sync(FULL, rs1, 2);
            l0 = l0 * al0 + rs0;
            l1 = l1 * al1 + rs1;
#pragma unroll
            for (int nc = 0; nc < 4; nc++) {
                oa[nc][0] *= al0; oa[nc][1] *= al0;
                oa[nc][2] *= al1; oa[nc][3] *= al1;
            }

            int src0 = (lane & ~3) | (c >> 1);
            int src1 = src0 + 2;
            float q00 = __shfl_sync(FULL, p0, src0), q01 = __shfl_sync(FULL, p1, src0);
            float q20 = __shfl_sync(FULL, p2, src0), q21 = __shfl_sync(FULL, p3, src0);
            float q02 = __shfl_sync(FULL, p0, src1), q03 = __shfl_sync(FULL, p1, src1);
            float q22 = __shfl_sync(FULL, p2, src1), q23 = __shfl_sync(FULL, p3, src1);
            float pa[4];
            pa[0] = (c & 1) ? q01 : q00;
            pa[1] = (c & 1) ? q21 : q20;
            pa[2] = (c & 1) ? q03 : q02;
            pa[3] = (c & 1) ? q23 : q22;

#pragma unroll
            for (int nc = 0; nc < 4; nc++) {
                float b[2];
                b[0] = Vt[(nc * 8 + r) * VSTR + n0 + c];
                b[1] = Vt[(nc * 8 + r) * VSTR + n0 + c + 4];
                mma_tf32(oa[nc], pa, b);
            }
        }

        float inv0 = 1.f / l0, inv1 = 1.f / l1;
        int orow0 = q0 + r, orow1 = q0 + r + 8;
#pragma unroll
        for (int nc = 0; nc < 4; nc++) {
            int col = hd * DH + nc * 8 + 2 * c;
            if (orow0 < SEQ) {
                __half* op = O + ((size_t)(g * SEQ + orow0)) * E_DIM + col;
                *(__half2*)op = __floats2half2_rn(oa[nc][0] * inv0, oa[nc][1] * inv0);
            }
            if (orow1 < SEQ) {
                __half* op = O + ((size_t)(g * SEQ + orow1)) * E_DIM + col;
                *(__half2*)op = __floats2half2_rn(oa[nc][2] * inv1, oa[nc][3] * inv1);
            }
        }
    }
}

// ---------------- layernorm: writes fp32 + fp16 -----------------------------
__global__ __launch_bounds__(256)
void ln_k(const float* __restrict__ in, const float* __restrict__ gam,
          const float* __restrict__ bet, float* __restrict__ out,
          __half* __restrict__ out16)
{
    const int row = blockIdx.x, t = threadIdx.x;
    const size_t base = (size_t)row * E_DIM;
    float v = in[base + t];

    __shared__ float red[8];
    __shared__ float bc;
    float s = v;
#pragma unroll
    for (int o = 16; o; o >>= 1) s += __shfl_xor_sync(0xffffffffu, s, o);
    if ((t & 31) == 0) red[t >> 5] = s;
    __syncthreads();
    if (t == 0) {
        float tt = 0.f;
#pragma unroll
        for (int i = 0; i < 8; i++) tt += red[i];
        bc = tt * (1.f / E_DIM);
    }
    __syncthreads();
    float mu = bc;
    float d = v - mu;
    __syncthreads();
    s = d * d;
#pragma unroll
    for (int o = 16; o; o >>= 1) s += __shfl_xor_sync(0xffffffffu, s, o);
    if ((t & 31) == 0) red[t >> 5] = s;
    __syncthreads();
    if (t == 0) {
        float tt = 0.f;
#pragma unroll
        for (int i = 0; i < 8; i++) tt += red[i];
        bc = rsqrtf(tt * (1.f / E_DIM) + LN_EPS);
    }
    __syncthreads();
    float o = d * bc * gam[t] + bet[t];
    out[base + t] = o;
    out16[base + t] = __float2half_rn(o);
}

// ---------------- final classifier -----------------------------------------
__global__ __launch_bounds__(256)
void fc_k(const float* __restrict__ w, const float* __restrict__ b,
          float* __restrict__ out)
{
    const int g = blockIdx.x, t = threadIdx.x;
    __shared__ float hrow[E_DIM];
    hrow[t] = g_h[(size_t)g * SEQ * E_DIM + t];
    __syncthreads();
    if (t < N_CLASSES) {
        float s = b[t];
        for (int e = 0; e < E_DIM; e++) s += hrow[e] * w[t * E_DIM + e];
        out[g * N_CLASSES + t] = s;
    }
}

// ---------------------------------------------------------------------------
extern "C" void kernel_launch(void* const* d_in, const int* in_sizes, int n_in,
                              void* d_out, int out_size)
{
    const float* x        = (const float*)d_in[0];
    const int*   edge_idx = (const int*)  d_in[1];
    // d_in[2] = batch (unused: layout is arange // NPG by construction)
    const float* pos_enc  = (const float*)d_in[3];
    const float* gcn_w    = (const float*)d_in[4];
    const float* gcn_b    = (const float*)d_in[5];
    const float* cls      = (const float*)d_in[6];
    const float* emb_w    = (const float*)d_in[7];
    const float* emb_b    = (const float*)d_in[8];
    const float* in_w     = (const float*)d_in[9];
    const float* in_b     = (const float*)d_in[10];
    const float* out_w    = (const float*)d_in[11];
    const float* out_b    = (const float*)d_in[12];
    const float* lin1_w   = (const float*)d_in[13];
    const float* lin1_b   = (const float*)d_in[14];
    const float* lin2_w   = (const float*)d_in[15];
    const float* lin2_b   = (const float*)d_in[16];
    const float* ln1_g    = (const float*)d_in[17];
    const float* ln1_beta = (const float*)d_in[18];
    const float* ln2_g    = (const float*)d_in[19];
    const float* ln2_beta = (const float*)d_in[20];
    const float* fc_w     = (const float*)d_in[21];
    const float* fc_b     = (const float*)d_in[22];
    float* out = (float*)d_out;

    void *p;
    float *xw, *emb, *h, *qkv, *tmp;
    __half *x16, *gcnw16, *gcn16, *embw16, *h16, *att16, *mlp16;
    __half *inw16, *outw16, *l1w16, *l2w16;
    cudaGetSymbolAddress(&p, g_xw);    xw    = (float*)p;
    cudaGetSymbolAddress(&p, g_emb);   emb   = (float*)p;
    cudaGetSymbolAddress(&p, g_h);     h     = (float*)p;
    cudaGetSymbolAddress(&p, g_qkv);   qkv   = (float*)p;
    cudaGetSymbolAddress(&p, g_tmp);   tmp   = (float*)p;
    cudaGetSymbolAddress(&p, g_x16);   x16   = (__half*)p;
    cudaGetSymbolAddress(&p, g_gcnw16);gcnw16= (__half*)p;
    cudaGetSymbolAddress(&p, g_gcn16); gcn16 = (__half*)p;
    cudaGetSymbolAddress(&p, g_embw16);embw16= (__half*)p;
    cudaGetSymbolAddress(&p, g_h16);   h16   = (__half*)p;
    cudaGetSymbolAddress(&p, g_att16); att16 = (__half*)p;
    cudaGetSymbolAddress(&p, g_mlp16); mlp16 = (__half*)p;
    cudaGetSymbolAddress(&p, g_inw16); inw16 = (__half*)p;
    cudaGetSymbolAddress(&p, g_outw16);outw16= (__half*)p;
    cudaGetSymbolAddress(&p, g_l1w16); l1w16 = (__half*)p;
    cudaGetSymbolAddress(&p, g_l2w16); l2w16 = (__half*)p;

    cudaFuncSetAttribute(gemm_h<0>, cudaFuncAttributeMaxDynamicSharedMemorySize, GH_SMEM);
    cudaFuncSetAttribute(gemm_h<1>, cudaFuncAttributeMaxDynamicSharedMemorySize, GH_SMEM);
    cudaFuncSetAttribute(attn_tc_k, cudaFuncAttributeMaxDynamicSharedMemorySize, ATTN_SMEM);

    // ---- convert GCN-front operands, GCN gemm at launch index 3 ----
    cvt_k<<<(N_NODES * F_IN) / 256, 256>>>(x, x16, N_NODES * F_IN);        // 0
    cvt_k<<<(F_IN * F_IN) / 256, 256>>>(gcn_w, gcnw16, F_IN * F_IN);       // 1
    deg_init_k<<<N_NODES / 256, 256>>>();                                  // 2
    gemm_h<0><<<dim3(F_IN / 128, N_NODES / 128), 256, GH_SMEM>>>(          // 3
        x16, gcnw16, nullptr, nullptr, xw, nullptr, F_IN, F_IN);
    deg_count_k<<<512, 256>>>(edge_idx);
    dinv_k<<<N_NODES / 256, 256>>>();
    gcn_self_k<<<(N_NODES * F_IN) / 256, 256>>>();
    gcn_scatter_k<<<2048, 256>>>(edge_idx);
    gcn_bias_relu_k<<<(N_NODES * F_IN) / 256, 256>>>(gcn_b);

    // ---- remaining weight conversions ----
    cvt_k<<<(E_DIM * F_IN) / 256, 256>>>(emb_w, embw16, E_DIM * F_IN);
    cvt_k<<<(N_LAYERS * 3 * E_DIM * E_DIM) / 256, 256>>>(in_w, inw16, N_LAYERS * 3 * E_DIM * E_DIM);
    cvt_k<<<(N_LAYERS * E_DIM * E_DIM) / 256, 256>>>(out_w, outw16, N_LAYERS * E_DIM * E_DIM);
    cvt_k<<<(N_LAYERS * MLP_DIM * E_DIM) / 256, 256>>>(lin1_w, l1w16, N_LAYERS * MLP_DIM * E_DIM);
    cvt_k<<<(N_LAYERS * E_DIM * MLP_DIM) / 256, 256>>>(lin2_w, l2w16, N_LAYERS * E_DIM * MLP_DIM);

    // ---- embedding + pos_enc, assemble tokens ----
    gemm_h<0><<<dim3(E_DIM / 128, N_NODES / 128), 256, GH_SMEM>>>(
        gcn16, embw16, emb_b, pos_enc, emb, nullptr, E_DIM, F_IN);
    assemble_k<<<(TOK * E_DIM) / 256, 256>>>(cls);

    // ---- transformer layers ----
    for (int l = 0; l < N_LAYERS; l++) {
        gemm_h<0><<<dim3(768 / 128, TOKP / 128), 256, GH_SMEM>>>(
            h16, inw16 + (size_t)l * 768 * E_DIM, in_b + l * 768,
            nullptr, qkv, nullptr, 768, E_DIM);
        attn_tc_k<<<N_GRAPHS * N_HEADS, 256, ATTN_SMEM>>>(qkv, att16);
        gemm_h<0><<<dim3(E_DIM / 128, TOKP / 128), 256, GH_SMEM>>>(
            att16, outw16 + (size_t)l * E_DIM * E_DIM, out_b + l * E_DIM,
            h, tmp, nullptr, E_DIM, E_DIM);
        ln_k<<<TOK, 256>>>(tmp, ln1_g + l * E_DIM, ln1_beta + l * E_DIM, h, h16);
        gemm_h<1><<<dim3(MLP_DIM / 128, TOKP / 128), 256, GH_SMEM>>>(
            h16, l1w16 + (size_t)l * MLP_DIM * E_DIM, lin1_b + l * MLP_DIM,
            nullptr, nullptr, mlp16, MLP_DIM, E_DIM);
        gemm_h<0><<<dim3(E_DIM / 128, TOKP / 128), 256, GH_SMEM>>>(
            mlp16, l2w16 + (size_t)l * E_DIM * MLP_DIM, lin2_b + l * E_DIM,
            h, tmp, nullptr, E_DIM, MLP_DIM);
        ln_k<<<TOK, 256>>>(tmp, ln2_g + l * E_DIM, ln2_beta + l * E_DIM, h, h16);
    }

    // ---- classifier head ----
    fc_k<<<N_GRAPHS, 256>>>(fc_w, fc_b, out);
}

// round 9
// speedup vs baseline: 4.8310x; 1.1480x over previous
#include <cuda_runtime.h>
#include <cuda_fp16.h>
#include <math.h>
#include <stdint.h>

#define N_NODES   16384
#define N_GRAPHS  64
#define NPG       256
#define F_IN      128
#define E_DIM     256
#define N_HEADS   8
#define DH        32
#define MLP_DIM   1024
#define N_LAYERS  4
#define N_CLASSES 10
#define N_EDGES   262144
#define SEQ       257                 // NODES_PER_GRAPH + 1 (cls)
#define TOK       (N_GRAPHS * SEQ)    // 16448
#define TOKP      16512               // padded to 129*128 for 128-row tiles
#define LN_EPS    1e-5f

// ---------------- scratch (static device globals, zero-initialized) --------
__device__ float g_xw [N_NODES * F_IN];
__device__ float g_gcn[N_NODES * F_IN];
__device__ float g_deg [N_NODES];
__device__ float g_dinv[N_NODES];
__device__ float g_emb[N_NODES * E_DIM];
__device__ float g_h  [TOKP * E_DIM];
__device__ float g_qkv[TOKP * 3 * E_DIM];   // reused as fp16 qkv (half the bytes)
__device__ float g_tmp[TOKP * E_DIM];

// fp16 operand mirrors
__device__ __half g_x16  [N_NODES * F_IN];
__device__ __half g_gcnw16[F_IN * F_IN];
__device__ __half g_gcn16[N_NODES * F_IN];
__device__ __half g_embw16[E_DIM * F_IN];
__device__ __half g_h16  [TOKP * E_DIM];
__device__ __half g_att16[TOKP * E_DIM];
__device__ __half g_mlp16[TOKP * MLP_DIM];
__device__ __half g_inw16 [N_LAYERS * 3 * E_DIM * E_DIM];
__device__ __half g_outw16[N_LAYERS * E_DIM * E_DIM];
__device__ __half g_l1w16 [N_LAYERS * MLP_DIM * E_DIM];
__device__ __half g_l2w16 [N_LAYERS * E_DIM * MLP_DIM];

// ===================== helpers =============================================
__device__ __forceinline__ uint32_t smem_u32(const void* p) {
    return (uint32_t)__cvta_generic_to_shared(p);
}
__device__ __forceinline__ void cp16s(uint32_t dst, const void* src) {
    asm volatile("cp.async.cg.shared.global [%0], [%1], 16;\n" :: "r"(dst), "l"(src));
}
#define CP_COMMIT() asm volatile("cp.async.commit_group;\n")

__device__ __forceinline__ void mma_f16(float* d, const uint32_t* a, const uint32_t* b) {
    asm volatile(
        "mma.sync.aligned.m16n8k16.row.col.f32.f16.f16.f32 "
        "{%0,%1,%2,%3}, {%4,%5,%6,%7}, {%8,%9}, {%0,%1,%2,%3};\n"
        : "+f"(d[0]), "+f"(d[1]), "+f"(d[2]), "+f"(d[3])
        : "r"(a[0]), "r"(a[1]), "r"(a[2]), "r"(a[3]), "r"(b[0]), "r"(b[1]));
}
__device__ __forceinline__ uint32_t packh2(float x, float y) {
    __half2 h = __floats2half2_rn(x, y);
    return *(uint32_t*)&h;
}

// ===================== fp16 HMMA GEMM =======================================
// C[M,N] = A[M,K] * B[N,K]^T (+bias over n)(+add fp32)(relu); A,B fp16.
// Block 128x128x32, 8 warps (2x4), warp tile 64x32, m16n8k16.
#define HROW 40
#define STG  (128 * HROW)               // halves per matrix per stage
#define GH_SMEM (4 * STG * 2)           // 2 stages x (A+B) x 2 bytes = 40960

template <int RELU>
__global__ __launch_bounds__(256, 2)
void gemm_h(const __half* __restrict__ A, const __half* __restrict__ B,
            const float* __restrict__ bias, const float* __restrict__ add,
            float* __restrict__ C32, __half* __restrict__ C16, int N, int K)
{
    extern __shared__ __half smh[];
    __half* As = smh;            // [2][STG]
    __half* Bs = smh + 2 * STG;  // [2][STG]

    const int tid = threadIdx.x;
    const int warp = tid >> 5, lane = tid & 31;
    const int wm = warp >> 2, wn = warp & 3;     // 2 x 4 warp grid
    const int r = lane >> 2, c = lane & 3;
    const int m0 = blockIdx.y * 128;
    const int n0 = blockIdx.x * 128;
    const int KT = K >> 5;

    float acc[4][4][4];
#pragma unroll
    for (int i = 0; i < 4; i++)
#pragma unroll
        for (int j = 0; j < 4; j++)
#pragma unroll
            for (int q = 0; q < 4; q++) acc[i][j][q] = 0.f;

    auto load_stage = [&](int kt, int s) {
        const __half* Ag = A + (size_t)m0 * K + kt * 32;
        const __half* Bg = B + (size_t)n0 * K + kt * 32;
        const uint32_t sa = smem_u32(&As[s * STG]);
        const uint32_t sb = smem_u32(&Bs[s * STG]);
#pragma unroll
        for (int i = 0; i < 2; i++) {
            int id = tid + 256 * i;
            int row = id >> 2, ch = id & 3;
            cp16s(sa + row * 80 + ch * 16, Ag + (size_t)row * K + ch * 8);
            cp16s(sb + row * 80 + ch * 16, Bg + (size_t)row * K + ch * 8);
        }
    };

    load_stage(0, 0);
    CP_COMMIT();

    for (int kt = 0; kt < KT; kt++) {
        const int s = kt & 1;
        if (kt + 1 < KT) {
            load_stage(kt + 1, s ^ 1);
            CP_COMMIT();
            asm volatile("cp.async.wait_group 1;\n");
        } else {
            asm volatile("cp.async.wait_group 0;\n");
        }
        __syncthreads();

        const uint32_t saBase = smem_u32(&As[s * STG]);
        const __half* Bst = &Bs[s * STG];
#pragma unroll
        for (int ks = 0; ks < 2; ks++) {
            uint32_t a[4][4];
#pragma unroll
            for (int ma = 0; ma < 4; ma++) {
                int mbase = wm * 64 + ma * 16;
                uint32_t addr = saBase + (mbase + (lane & 15)) * 80
                              + ks * 32 + ((lane >> 4) & 1) * 16;
                asm volatile(
                    "ldmatrix.sync.aligned.m8n8.x4.shared.b16 {%0,%1,%2,%3}, [%4];"
                    : "=r"(a[ma][0]), "=r"(a[ma][1]), "=r"(a[ma][2]), "=r"(a[ma][3])
                    : "r"(addr));
            }
            uint32_t b[4][2];
#pragma unroll
            for (int na = 0; na < 4; na++) {
                int n = wn * 32 + na * 8 + r;
                const __half* bp = Bst + n * HROW + ks * 16 + c * 2;
                b[na][0] = *(const uint32_t*)(bp);
                b[na][1] = *(const uint32_t*)(bp + 8);
            }
#pragma unroll
            for (int ma = 0; ma < 4; ma++)
#pragma unroll
                for (int na = 0; na < 4; na++)
                    mma_f16(acc[ma][na], a[ma], b[na]);
        }
        __syncthreads();
    }

#pragma unroll
    for (int ma = 0; ma < 4; ma++) {
        int mlo = m0 + wm * 64 + ma * 16 + r;
        int mhi = mlo + 8;
#pragma unroll
        for (int na = 0; na < 4; na++) {
            int n = n0 + wn * 32 + na * 8 + c * 2;
            float b0 = bias ? bias[n] : 0.f;
            float b1 = bias ? bias[n + 1] : 0.f;
            float v0 = acc[ma][na][0] + b0;
            float v1 = acc[ma][na][1] + b1;
            float v2 = acc[ma][na][2] + b0;
            float v3 = acc[ma][na][3] + b1;
            size_t ilo = (size_t)mlo * N + n;
            size_t ihi = (size_t)mhi * N + n;
            if (add) {
                float2 alo = *(const float2*)&add[ilo];
                float2 ahi = *(const float2*)&add[ihi];
                v0 += alo.x; v1 += alo.y; v2 += ahi.x; v3 += ahi.y;
            }
            if (RELU) {
                v0 = v0 > 0.f ? v0 : 0.f; v1 = v1 > 0.f ? v1 : 0.f;
                v2 = v2 > 0.f ? v2 : 0.f; v3 = v3 > 0.f ? v3 : 0.f;
            }
            if (C32) {
                *(float2*)&C32[ilo] = make_float2(v0, v1);
                *(float2*)&C32[ihi] = make_float2(v2, v3);
            }
            if (C16) {
                *(__half2*)&C16[ilo] = __floats2half2_rn(v0, v1);
                *(__half2*)&C16[ihi] = __floats2half2_rn(v2, v3);
            }
        }
    }
}

// ---------------- fp32 -> fp16 convert -------------------------------------
__global__ void cvt_k(const float* __restrict__ s, __half* __restrict__ d, int n) {
    int i = blockIdx.x * blockDim.x + threadIdx.x;
    if (i < n) d[i] = __float2half_rn(s[i]);
}

// ---------------- GCN pieces ----------------------------------------------
__global__ void deg_init_k() {
    int i = blockIdx.x * blockDim.x + threadIdx.x;
    if (i < N_NODES) g_deg[i] = 1.0f;
}
__global__ void deg_count_k(const int* __restrict__ ei) {
    int i = blockIdx.x * blockDim.x + threadIdx.x;
    for (; i < N_EDGES; i += gridDim.x * blockDim.x)
        atomicAdd(&g_deg[ei[N_EDGES + i]], 1.0f);
}
__global__ void dinv_k() {
    int i = blockIdx.x * blockDim.x + threadIdx.x;
    if (i < N_NODES) g_dinv[i] = rsqrtf(g_deg[i]);
}
__global__ void gcn_self_k() {
    int i = blockIdx.x * blockDim.x + threadIdx.x;
    if (i < N_NODES * F_IN) {
        int n = i >> 7;
        float d = g_dinv[n];
        g_gcn[i] = d * d * g_xw[i];
    }
}
__global__ void gcn_scatter_k(const int* __restrict__ ei) {
    int warp = (blockIdx.x * blockDim.x + threadIdx.x) >> 5;
    int lane = threadIdx.x & 31;
    int nwarp = (gridDim.x * blockDim.x) >> 5;
    for (int e = warp; e < N_EDGES; e += nwarp) {
        int row = ei[e];
        int col = ei[N_EDGES + e];
        float nm = g_dinv[row] * g_dinv[col];
        const float* src = g_xw + (size_t)row * F_IN;
        float* dst = g_gcn + (size_t)col * F_IN;
#pragma unroll
        for (int j = 0; j < 4; j++)
            atomicAdd(&dst[lane + 32 * j], nm * src[lane + 32 * j]);
    }
}
__global__ void gcn_bias_relu_k(const float* __restrict__ b) {
    int i = blockIdx.x * blockDim.x + threadIdx.x;
    if (i < N_NODES * F_IN) {
        float v = g_gcn[i] + b[i & 127];
        g_gcn16[i] = __float2half_rn(v > 0.f ? v : 0.f);
    }
}

// ---------------- assemble H (cls token + embedded nodes) ------------------
__global__ void assemble_k(const float* __restrict__ cls) {
    int idx = blockIdx.x * blockDim.x + threadIdx.x;   // TOK*E_DIM exact
    int row = idx >> 8, col = idx & 255;
    int g = row / SEQ, s = row - g * SEQ;
    float v = (s == 0) ? cls[col]
                       : g_emb[((size_t)(g * NPG + s - 1)) * E_DIM + col];
    g_h[idx] = v;
    g_h16[idx] = __float2half_rn(v);
}

// ============== fp16 flash attention: block per (graph, head) ===============
// m16n8k16; 16-key chunks; S c-frag maps directly onto PV a-frag (no shuffle).
#define SEQP2 272
#define KSH 40          // Ks stride in halves
#define VSH 280         // Vt stride in halves

__global__ __launch_bounds__(256)
void attn_h_k(const __half* __restrict__ qkv, __half* __restrict__ O)
{
    const int g  = blockIdx.x >> 3;
    const int hd = blockIdx.x & 7;
    __shared__ __half Ks[SEQP2 * KSH];   // [key][d]
    __shared__ __half Vt[32 * VSH];      // [d][key]

    const int tid = threadIdx.x, warp = tid >> 5, lane = tid & 31;
    const int r = lane >> 2, c = lane & 3;
    const float scale = 0.17677669529663687f;   // 1/sqrt(32)
    const unsigned FULL = 0xffffffffu;

    for (int i = tid; i < SEQP2 * 32; i += 256) {
        int key = i >> 5, d = i & 31;
        __half kv = __float2half_rn(0.f), vv = kv;
        if (key < SEQ) {
            const __half* p = qkv + ((size_t)(g * SEQ + key)) * 768 + E_DIM + hd * DH + d;
            kv = p[0]; vv = p[E_DIM];
        }
        Ks[key * KSH + d] = kv;
        Vt[d * VSH + key] = vv;
    }
    __syncthreads();

    for (int qt = warp; qt < 17; qt += 8) {
        const int q0 = qt * 16;
        int row0 = q0 + r;      if (row0 > 256) row0 = 256;
        int row1 = q0 + r + 8;  if (row1 > 256) row1 = 256;
        const __half* Q0 = qkv + ((size_t)(g * SEQ + row0)) * 768 + hd * DH;
        const __half* Q1 = qkv + ((size_t)(g * SEQ + row1)) * 768 + hd * DH;

        uint32_t qa[2][4];
#pragma unroll
        for (int ks = 0; ks < 2; ks++) {
            qa[ks][0] = *(const uint32_t*)&Q0[ks * 16 + 2 * c];
            qa[ks][1] = *(const uint32_t*)&Q1[ks * 16 + 2 * c];
            qa[ks][2] = *(const uint32_t*)&Q0[ks * 16 + 2 * c + 8];
            qa[ks][3] = *(const uint32_t*)&Q1[ks * 16 + 2 * c + 8];
        }

        float m0 = -1e30f, m1 = -1e30f, l0 = 0.f, l1 = 0.f;
        float oa[4][4];
#pragma unroll
        for (int nt = 0; nt < 4; nt++)
#pragma unroll
            for (int q = 0; q < 4; q++) oa[nt][q] = 0.f;

        for (int n0 = 0; n0 < SEQP2; n0 += 16) {
            // ---- S = Q K^T, 16 keys (two n8 tiles), fp32 c-frags ----
            float st[2][4] = {{0.f,0.f,0.f,0.f},{0.f,0.f,0.f,0.f}};
#pragma unroll
            for (int tile = 0; tile < 2; tile++) {
                int key = n0 + tile * 8 + r;
#pragma unroll
                for (int ks = 0; ks < 2; ks++) {
                    uint32_t b[2];
                    b[0] = *(const uint32_t*)&Ks[key * KSH + ks * 16 + 2 * c];
                    b[1] = *(const uint32_t*)&Ks[key * KSH + ks * 16 + 2 * c + 8];
                    mma_f16(st[tile], qa[ks], b);
                }
            }
            // scale + mask padded keys
#pragma unroll
            for (int tile = 0; tile < 2; tile++) {
                int col = n0 + tile * 8 + 2 * c;
                st[tile][0] = (col     < SEQ) ? st[tile][0] * scale : -1e30f;
                st[tile][1] = (col + 1 < SEQ) ? st[tile][1] * scale : -1e30f;
                st[tile][2] = (col     < SEQ) ? st[tile][2] * scale : -1e30f;
                st[tile][3] = (col + 1 < SEQ) ? st[tile][3] * scale : -1e30f;
            }

            // ---- online softmax (rows r and r+8) ----
            float cm0 = fmaxf(fmaxf(st[0][0], st[0][1]), fmaxf(st[1][0], st[1][1]));
            float cm1 = fmaxf(fmaxf(st[0][2], st[0][3]), fmaxf(st[1][2], st[1][3]));
            cm0 = fmaxf(cm0, __shfl_xor_sync(FULL, cm0, 1));
            cm0 = fmaxf(cm0, __shfl_xor_sync(FULL, cm0, 2));
            cm1 = fmaxf(cm1, __shfl_xor_sync(FULL, cm1, 1));
            cm1 = fmaxf(cm1, __shfl_xor_sync(FULL, cm1, 2));
            float nm0 = fmaxf(m0, cm0), nm1 = fmaxf(m1, cm1);
            float al0 = __expf(m0 - nm0), al1 = __expf(m1 - nm1);
            m0 = nm0; m1 = nm1;
            float p00 = __expf(st[0][0] - nm0), p01 = __expf(st[0][1] - nm0);
            float p02 = __expf(st[0][2] - nm1), p03 = __expf(st[0][3] - nm1);
            float p10 = __expf(st[1][0] - nm0), p11 = __expf(st[1][1] - nm0);
            float p12 = __expf(st[1][2] - nm1), p13 = __expf(st[1][3] - nm1);
            float rs0 = p00 + p01 + p10 + p11;
            float rs1 = p02 + p03 + p12 + p13;
            rs0 += __shfl_xor_sync(FULL, rs0, 1);
            rs0 += __shfl_xor_sync(FULL, rs0, 2);
            rs1 += __shfl_xor_sync(FULL, rs1, 1);
            rs1 += __shfl_xor_sync(FULL, rs1, 2);
            l0 = l0 * al0 + rs0;
            l1 = l1 * al1 + rs1;
#pragma unroll
            for (int nt = 0; nt < 4; nt++) {
                oa[nt][0] *= al0; oa[nt][1] *= al0;
                oa[nt][2] *= al1; oa[nt][3] *= al1;
            }

            // ---- P a-frag directly from c-frags (no shuffles) ----
            uint32_t pa[4];
            pa[0] = packh2(p00, p01);   // P[r][2c..] keys tile0
            pa[1] = packh2(p02, p03);   // P[r+8][2c..] tile0
            pa[2] = packh2(p10, p11);   // P[r][2c+8..] tile1
            pa[3] = packh2(p12, p13);   // P[r+8][2c+8..] tile1

            // ---- O += P V ----
#pragma unroll
            for (int nt = 0; nt < 4; nt++) {
                int n = nt * 8 + r;
                uint32_t b[2];
                b[0] = *(const uint32_t*)&Vt[n * VSH + n0 + 2 * c];
                b[1] = *(const uint32_t*)&Vt[n * VSH + n0 + 2 * c + 8];
                mma_f16(oa[nt], pa, b);
            }
        }

        // ---- normalize and store fp16 ----
        float inv0 = 1.f / l0, inv1 = 1.f / l1;
        int orow0 = q0 + r, orow1 = q0 + r + 8;
#pragma unroll
        for (int nt = 0; nt < 4; nt++) {
            int col = hd * DH + nt * 8 + 2 * c;
            if (orow0 < SEQ) {
                __half* op = O + ((size_t)(g * SEQ + orow0)) * E_DIM + col;
                *(__half2*)op = __floats2half2_rn(oa[nt][0] * inv0, oa[nt][1] * inv0);
            }
            if (orow1 < SEQ) {
                __half* op = O + ((size_t)(g * SEQ + orow1)) * E_DIM + col;
                *(__half2*)op = __floats2half2_rn(oa[nt][2] * inv1, oa[nt][3] * inv1);
            }
        }
    }
}

// ---------------- layernorm: writes fp32 + fp16 -----------------------------
__global__ __launch_bounds__(256)
void ln_k(const float* __restrict__ in, const float* __restrict__ gam,
          const float* __restrict__ bet, float* __restrict__ out,
          __half* __restrict__ out16)
{
    const int row = blockIdx.x, t = threadIdx.x;
    const size_t base = (size_t)row * E_DIM;
    float v = in[base + t];

    __shared__ float red[8];
    __shared__ float bc;
    float s = v;
#pragma unroll
    for (int o = 16; o; o >>= 1) s += __shfl_xor_sync(0xffffffffu, s, o);
    if ((t & 31) == 0) red[t >> 5] = s;
    __syncthreads();
    if (t == 0) {
        float tt = 0.f;
#pragma unroll
        for (int i = 0; i < 8; i++) tt += red[i];
        bc = tt * (1.f / E_DIM);
    }
    __syncthreads();
    float mu = bc;
    float d = v - mu;
    __syncthreads();
    s = d * d;
#pragma unroll
    for (int o = 16; o; o >>= 1) s += __shfl_xor_sync(0xffffffffu, s, o);
    if ((t & 31) == 0) red[t >> 5] = s;
    __syncthreads();
    if (t == 0) {
        float tt = 0.f;
#pragma unroll
        for (int i = 0; i < 8; i++) tt += red[i];
        bc = rsqrtf(tt * (1.f / E_DIM) + LN_EPS);
    }
    __syncthreads();
    float o = d * bc * gam[t] + bet[t];
    out[base + t] = o;
    out16[base + t] = __float2half_rn(o);
}

// ---------------- final classifier -----------------------------------------
__global__ __launch_bounds__(256)
void fc_k(const float* __restrict__ w, const float* __restrict__ b,
          float* __restrict__ out)
{
    const int g = blockIdx.x, t = threadIdx.x;
    __shared__ float hrow[E_DIM];
    hrow[t] = g_h[(size_t)g * SEQ * E_DIM + t];
    __syncthreads();
    if (t < N_CLASSES) {
        float s = b[t];
        for (int e = 0; e < E_DIM; e++) s += hrow[e] * w[t * E_DIM + e];
        out[g * N_CLASSES + t] = s;
    }
}

// ---------------------------------------------------------------------------
extern "C" void kernel_launch(void* const* d_in, const int* in_sizes, int n_in,
                              void* d_out, int out_size)
{
    const float* x        = (const float*)d_in[0];
    const int*   edge_idx = (const int*)  d_in[1];
    // d_in[2] = batch (unused: layout is arange // NPG by construction)
    const float* pos_enc  = (const float*)d_in[3];
    const float* gcn_w    = (const float*)d_in[4];
    const float* gcn_b    = (const float*)d_in[5];
    const float* cls      = (const float*)d_in[6];
    const float* emb_w    = (const float*)d_in[7];
    const float* emb_b    = (const float*)d_in[8];
    const float* in_w     = (const float*)d_in[9];
    const float* in_b     = (const float*)d_in[10];
    const float* out_w    = (const float*)d_in[11];
    const float* out_b    = (const float*)d_in[12];
    const float* lin1_w   = (const float*)d_in[13];
    const float* lin1_b   = (const float*)d_in[14];
    const float* lin2_w   = (const float*)d_in[15];
    const float* lin2_b   = (const float*)d_in[16];
    const float* ln1_g    = (const float*)d_in[17];
    const float* ln1_beta = (const float*)d_in[18];
    const float* ln2_g    = (const float*)d_in[19];
    const float* ln2_beta = (const float*)d_in[20];
    const float* fc_w     = (const float*)d_in[21];
    const float* fc_b     = (const float*)d_in[22];
    float* out = (float*)d_out;

    void *p;
    float *xw, *emb, *h, *tmp;
    __half *qkv16;
    __half *x16, *gcnw16, *gcn16, *embw16, *h16, *att16, *mlp16;
    __half *inw16, *outw16, *l1w16, *l2w16;
    cudaGetSymbolAddress(&p, g_xw);    xw    = (float*)p;
    cudaGetSymbolAddress(&p, g_emb);   emb   = (float*)p;
    cudaGetSymbolAddress(&p, g_h);     h     = (float*)p;
    cudaGetSymbolAddress(&p, g_qkv);   qkv16 = (__half*)p;   // fp16 view
    cudaGetSymbolAddress(&p, g_tmp);   tmp   = (float*)p;
    cudaGetSymbolAddress(&p, g_x16);   x16   = (__half*)p;
    cudaGetSymbolAddress(&p, g_gcnw16);gcnw16= (__half*)p;
    cudaGetSymbolAddress(&p, g_gcn16); gcn16 = (__half*)p;
    cudaGetSymbolAddress(&p, g_embw16);embw16= (__half*)p;
    cudaGetSymbolAddress(&p, g_h16);   h16   = (__half*)p;
    cudaGetSymbolAddress(&p, g_att16); att16 = (__half*)p;
    cudaGetSymbolAddress(&p, g_mlp16); mlp16 = (__half*)p;
    cudaGetSymbolAddress(&p, g_inw16); inw16 = (__half*)p;
    cudaGetSymbolAddress(&p, g_outw16);outw16= (__half*)p;
    cudaGetSymbolAddress(&p, g_l1w16); l1w16 = (__half*)p;
    cudaGetSymbolAddress(&p, g_l2w16); l2w16 = (__half*)p;

    cudaFuncSetAttribute(gemm_h<0>, cudaFuncAttributeMaxDynamicSharedMemorySize, GH_SMEM);
    cudaFuncSetAttribute(gemm_h<1>, cudaFuncAttributeMaxDynamicSharedMemorySize, GH_SMEM);

    // ---- convert GCN-front operands, GCN gemm at launch index 3 ----
    cvt_k<<<(N_NODES * F_IN) / 256, 256>>>(x, x16, N_NODES * F_IN);        // 0
    cvt_k<<<(F_IN * F_IN) / 256, 256>>>(gcn_w, gcnw16, F_IN * F_IN);       // 1
    deg_init_k<<<N_NODES / 256, 256>>>();                                  // 2
    gemm_h<0><<<dim3(F_IN / 128, N_NODES / 128), 256, GH_SMEM>>>(          // 3
        x16, gcnw16, nullptr, nullptr, xw, nullptr, F_IN, F_IN);
    deg_count_k<<<512, 256>>>(edge_idx);
    dinv_k<<<N_NODES / 256, 256>>>();
    gcn_self_k<<<(N_NODES * F_IN) / 256, 256>>>();
    gcn_scatter_k<<<2048, 256>>>(edge_idx);
    gcn_bias_relu_k<<<(N_NODES * F_IN) / 256, 256>>>(gcn_b);

    // ---- remaining weight conversions ----
    cvt_k<<<(E_DIM * F_IN) / 256, 256>>>(emb_w, embw16, E_DIM * F_IN);
    cvt_k<<<(N_LAYERS * 3 * E_DIM * E_DIM) / 256, 256>>>(in_w, inw16, N_LAYERS * 3 * E_DIM * E_DIM);
    cvt_k<<<(N_LAYERS * E_DIM * E_DIM) / 256, 256>>>(out_w, outw16, N_LAYERS * E_DIM * E_DIM);
    cvt_k<<<(N_LAYERS * MLP_DIM * E_DIM) / 256, 256>>>(lin1_w, l1w16, N_LAYERS * MLP_DIM * E_DIM);
    cvt_k<<<(N_LAYERS * E_DIM * MLP_DIM) / 256, 256>>>(lin2_w, l2w16, N_LAYERS * E_DIM * MLP_DIM);

    // ---- embedding + pos_enc, assemble tokens ----
    gemm_h<0><<<dim3(E_DIM / 128, N_NODES / 128), 256, GH_SMEM>>>(
        gcn16, embw16, emb_b, pos_enc, emb, nullptr, E_DIM, F_IN);
    assemble_k<<<(TOK * E_DIM) / 256, 256>>>(cls);

    // ---- transformer layers ----
    for (int l = 0; l < N_LAYERS; l++) {
        gemm_h<0><<<dim3(768 / 128, TOKP / 128), 256, GH_SMEM>>>(
            h16, inw16 + (size_t)l * 768 * E_DIM, in_b + l * 768,
            nullptr, nullptr, qkv16, 768, E_DIM);
        attn_h_k<<<N_GRAPHS * N_HEADS, 256>>>(qkv16, att16);
        gemm_h<0><<<dim3(E_DIM / 128, TOKP / 128), 256, GH_SMEM>>>(
            att16, outw16 + (size_t)l * E_DIM * E_DIM, out_b + l * E_DIM,
            h, tmp, nullptr, E_DIM, E_DIM);
        ln_k<<<TOK, 256>>>(tmp, ln1_g + l * E_DIM, ln1_beta + l * E_DIM, h, h16);
        gemm_h<1><<<dim3(MLP_DIM / 128, TOKP / 128), 256, GH_SMEM>>>(
            h16, l1w16 + (size_t)l * MLP_DIM * E_DIM, lin1_b + l * MLP_DIM,
            nullptr, nullptr, mlp16, MLP_DIM, E_DIM);
        gemm_h<0><<<dim3(E_DIM / 128, TOKP / 128), 256, GH_SMEM>>>(
            mlp16, l2w16 + (size_t)l * E_DIM * MLP_DIM, lin2_b + l * E_DIM,
            h, tmp, nullptr, E_DIM, MLP_DIM);
        ln_k<<<TOK, 256>>>(tmp, ln2_g + l * E_DIM, ln2_beta + l * E_DIM, h, h16);
    }

    // ---- classifier head ----
    fc_k<<<N_GRAPHS, 256>>>(fc_w, fc_b, out);
}